// round 13
// baseline (speedup 1.0000x reference)
#include <cuda_runtime.h>
#include <cuda_bf16.h>
#include <math.h>
#include <cstdint>

#define NB 4096

// ----- scratch (device globals; no allocations) -----
__device__ float  g_h1max[NB * 32 * 196];
__device__ float  g_h1min[NB * 32 * 196];
__device__ float  g_o2max[NB * 64 * 49];
__device__ float  g_o2min[NB * 64 * 49];
__device__ float  g_feat[NB * 128];
__device__ float  g_part1[NB * 64];
__device__ float  g_part2[NB * 128];
__device__ float  g_bn1[64];
__device__ float  g_bn2[128];
__device__ float  g_fcpart[8 * NB * 128];
__device__ float  g_partA[64 * 129 * 129];
__device__ float  g_partB[64 * 1290];
__device__ double g_A[129 * 129];
__device__ double g_Bm[1290];
__device__ float  g_W[1290];
__device__ uint32_t g_Wfh[21888];      // 72 krows x 76 (padded) x uint2
__device__ uint32_t g_Wfl[21888];

extern __shared__ char dynsmem[];

__device__ __forceinline__ void mma_bf16(float* c, uint32_t a0, uint32_t a1,
                                         uint32_t a2, uint32_t a3,
                                         uint32_t b0, uint32_t b1)
{
    asm volatile(
        "mma.sync.aligned.m16n8k16.row.col.f32.bf16.bf16.f32 "
        "{%0,%1,%2,%3}, {%4,%5,%6,%7}, {%8,%9}, {%0,%1,%2,%3};"
        : "+f"(c[0]), "+f"(c[1]), "+f"(c[2]), "+f"(c[3])
        : "r"(a0), "r"(a1), "r"(a2), "r"(a3), "r"(b0), "r"(b1));
}

__device__ __forceinline__ uint32_t packbf(float v0, float v1)
{
    __nv_bfloat162 p = __floats2bfloat162_rn(v0, v1);
    return *(uint32_t*)&p;
}

// ===== conv1 single pass: raw-conv window max/min + BN stats =====
__global__ __launch_bounds__(224) void k_conv1_mmx(
    const float* __restrict__ x, const float* __restrict__ w, const float* __restrict__ bias)
{
    __shared__ float simg[900], sw[288], sb[32], wred[7][64];
    int n = blockIdx.x, tid = threadIdx.x;
    for (int i = tid; i < 900; i += 224) simg[i] = 0.f;
    for (int i = tid; i < 288; i += 224) sw[i] = w[i];
    if (tid < 32) sb[tid] = bias[tid];
    __syncthreads();
    const float* xi = x + n * 784;
    for (int i = tid; i < 784; i += 224)
        simg[(i / 28 + 1) * 30 + (i % 28) + 1] = xi[i];
    __syncthreads();

    float ls[32], lq[32];
#pragma unroll
    for (int c = 0; c < 32; c++) { ls[c] = 0.f; lq[c] = 0.f; }

    if (tid < 196) {
        int py = tid / 14, px = tid % 14;
        float patch[16];
#pragma unroll
        for (int dy = 0; dy < 4; dy++)
#pragma unroll
            for (int dx = 0; dx < 4; dx++)
                patch[dy * 4 + dx] = simg[(2 * py + dy) * 30 + 2 * px + dx];
#pragma unroll
        for (int oc = 0; oc < 32; oc++) {
            float v[4];
#pragma unroll
            for (int dy = 0; dy < 2; dy++)
#pragma unroll
                for (int dx = 0; dx < 2; dx++) {
                    float a = sb[oc];
#pragma unroll
                    for (int ky = 0; ky < 3; ky++)
#pragma unroll
                        for (int kx = 0; kx < 3; kx++)
                            a = fmaf(sw[oc * 9 + ky * 3 + kx],
                                     patch[(dy + ky) * 4 + dx + kx], a);
                    v[dy * 2 + dx] = a;
                }
            float mx = fmaxf(fmaxf(v[0], v[1]), fmaxf(v[2], v[3]));
            float mn = fminf(fminf(v[0], v[1]), fminf(v[2], v[3]));
            g_h1max[(n * 32 + oc) * 196 + tid] = mx;
            g_h1min[(n * 32 + oc) * 196 + tid] = mn;
            ls[oc] += (v[0] + v[1]) + (v[2] + v[3]);
            lq[oc] = fmaf(v[0], v[0], fmaf(v[1], v[1], fmaf(v[2], v[2], fmaf(v[3], v[3], lq[oc]))));
        }
    }
    int lane = tid & 31, wid = tid >> 5;
#pragma unroll
    for (int oc = 0; oc < 32; oc++) {
        float s = ls[oc], q = lq[oc];
#pragma unroll
        for (int o = 16; o > 0; o >>= 1) {
            s += __shfl_down_sync(0xffffffffu, s, o);
            q += __shfl_down_sync(0xffffffffu, q, o);
        }
        if (lane == 0) { wred[wid][oc] = s; wred[wid][32 + oc] = q; }
    }
    __syncthreads();
    if (tid < 64) {
        float s = 0.f;
#pragma unroll
        for (int w7 = 0; w7 < 7; w7++) s += wred[w7][tid];
        g_part1[n * 64 + tid] = s;
    }
}

// ===== BN finalize =====
__global__ __launch_bounds__(256) void k_bnfinal(
    const float* __restrict__ gamma, const float* __restrict__ beta,
    const float* __restrict__ part, float* __restrict__ bn, int nc, float invN)
{
    int c = blockIdx.x, tid = threadIdx.x;
    float s = 0.f, q = 0.f;
    for (int r = tid; r < NB; r += 256) {
        s += part[r * 2 * nc + c];
        q += part[r * 2 * nc + nc + c];
    }
    __shared__ float ss[256], sq[256];
    ss[tid] = s; sq[tid] = q; __syncthreads();
    for (int o = 128; o > 0; o >>= 1) {
        if (tid < o) { ss[tid] += ss[tid + o]; sq[tid] += sq[tid + o]; }
        __syncthreads();
    }
    if (tid == 0) {
        float mean = ss[0] * invN;
        float var = sq[0] * invN - mean * mean;
        float scale = gamma[c] * rsqrtf(var + 1e-5f);
        bn[c] = scale;
        bn[nc + c] = beta[c] - mean * scale;
    }
}

// ===== weight fragment prep (once): pair-packed hi/lo, PADDED stride 76 =====
// krow = kt*4 + t (72 rows), nb in [0,76). pair = (Wrow[kt*8+t][nb], Wrow[kt*8+t+4][nb])
__global__ __launch_bounds__(256) void k_prepw(const float* __restrict__ cw)
{
    int i = blockIdx.x * 256 + threadIdx.x;
    if (i >= 21888) return;
    int pair = i >> 1, u = i & 1;
    int krow = pair / 76, nb = pair % 76;
    int kt = krow >> 2, t = krow & 3;
    uint32_t hw = 0, lw = 0;
    if (nb < 64) {
        int srow = kt * 8 + t + 4 * u;
        int s9 = srow >> 4, j = srow & 15;
        float w0 = cw[nb * 288 + 2 * j * 9 + s9];
        float w1 = cw[nb * 288 + (2 * j + 1) * 9 + s9];
        __nv_bfloat16 h0 = __float2bfloat16_rn(w0);
        __nv_bfloat16 h1 = __float2bfloat16_rn(w1);
        __nv_bfloat162 hp; hp.x = h0; hp.y = h1;
        hw = *(uint32_t*)&hp;
        lw = packbf(w0 - __bfloat162float(h0), w1 - __bfloat162float(h1));
    }
    g_Wfh[i] = hw;
    g_Wfl[i] = lw;
}

// ===================== conv2 via mma.sync bf16 split (HMMA), v5 =====================
// A interleaved hi/lo uint4 (LDS.128, conflict-free); B padded stride 76 (conflict-free).
// smem (bytes): TA 0 (55296), Wfh 55296 (43776), Wfl 99072 (43776), sD 142848 (50432).
// total 193280.
#define C2M_SMEM 193280

__global__ __launch_bounds__(512, 1) void k_conv2_mma(const float* __restrict__ cb)
{
    uint4* TA  = (uint4*)dynsmem;                    // [288 rows][12]: (hi0,hi1,lo0,lo1)
    uint2* Wfh = (uint2*)(dynsmem + 55296);          // [72 krows][76]
    uint2* Wfl = (uint2*)(dynsmem + 99072);
    float* sD  = (float*)(dynsmem + 142848);         // [64][197]
    __shared__ float ssc1[32], ssh1[32], sbias[64];

    int n = blockIdx.x, tid = threadIdx.x;
    int lane = tid & 31, w = tid >> 5;
    int g = lane >> 2, t = lane & 3;

    if (tid < 32) { ssc1[tid] = g_bn1[tid]; ssh1[tid] = g_bn1[32 + tid]; }
    if (tid < 64) sbias[tid] = cb[tid];

    {
        const uint2* gh = (const uint2*)g_Wfh;
        const uint2* gl = (const uint2*)g_Wfl;
        for (int i = tid; i < 5472; i += 512) { Wfh[i] = gh[i]; Wfl[i] = gl[i]; }
    }
    for (int i = tid; i < 3456; i += 512)
        TA[i] = make_uint4(0u, 0u, 0u, 0u);
    __syncthreads();

    // input: BN1 select + relu, split hi/lo into interleaved uint4 layout
    const float* mxp = g_h1max + n * 6272;
    const float* mnp = g_h1min + n * 6272;
    __nv_bfloat16* T16 = (__nv_bfloat16*)TA;
    for (int i = tid; i < 6272; i += 512) {
        int ci = i / 196, p = i % 196;
        float sc = ssc1[ci], sh = ssh1[ci];
        float base = (sc >= 0.f) ? mxp[i] : mnp[i];
        float v = fmaxf(fmaf(sc, base, sh), 0.f);
        __nv_bfloat16 hbf = __float2bfloat16_rn(v);
        float lf = v - __bfloat162float(hbf);
        int j = ci >> 1, hh = j >> 3, r = j & 7;
        int tt = r & 3, u = r >> 2;
        int row = (p / 14 + 1) * 16 + (p % 14 + 1);
        int e4 = row * 12 + hh * 4 + tt;               // uint4 element
        T16[(e4 * 4 + u) * 2 + (ci & 1)]     = hbf;    // hi words 0..1
        T16[(e4 * 4 + 2 + u) * 2 + (ci & 1)] = __float2bfloat16_rn(lf);  // lo words 2..3
    }
    __syncthreads();

    // warp = (mg, nq): mg owns m-tiles mg+4*mi (dummy replays), nq owns n-tiles {2nq,2nq+1}
    int mg = w & 3, nq = w >> 2;
    int pixa[4], pixb[4], mas[4];
#pragma unroll
    for (int mi = 0; mi < 4; mi++) {
        int mt = mg + 4 * mi;
        bool real = mt < 13;
        int mt2 = real ? mt : mg;
        int ma = mt2 * 16 + g;
        int mb = ma + 8;
        mas[mi] = real ? ma : -1;
        pixa[mi] = ((ma / 14) * 16 + (ma % 14)) * 12;
        pixb[mi] = ((mb / 14) * 16 + (mb % 14)) * 12;
    }
    float acc[4][2][4];
#pragma unroll
    for (int mi = 0; mi < 4; mi++)
#pragma unroll
        for (int nt = 0; nt < 2; nt++)
#pragma unroll
            for (int c = 0; c < 4; c++) acc[mi][nt][c] = 0.f;

    int nb0 = nq * 16 + g;

#pragma unroll 9
    for (int kt = 0; kt < 18; kt++) {
        int s = kt >> 1, hh = kt & 1;
        int off12 = ((s / 3) * 16 + (s % 3)) * 12;
        int wbase = (kt * 4 + t) * 76 + nb0;
        uint2 bh[2], bl[2];
#pragma unroll
        for (int nt = 0; nt < 2; nt++) {
            bh[nt] = Wfh[wbase + nt * 8];
            bl[nt] = Wfl[wbase + nt * 8];
        }
        int abase = off12 + hh * 4 + t;
#pragma unroll
        for (int mi = 0; mi < 4; mi++) {
            uint4 ua = TA[pixa[mi] + abase];
            uint4 ub = TA[pixb[mi] + abase];
#pragma unroll
            for (int nt = 0; nt < 2; nt++) {
                mma_bf16(acc[mi][nt], ua.x, ub.x, ua.y, ub.y, bh[nt].x, bh[nt].y);
                mma_bf16(acc[mi][nt], ua.x, ub.x, ua.y, ub.y, bl[nt].x, bl[nt].y);
                mma_bf16(acc[mi][nt], ua.z, ub.z, ua.w, ub.w, bh[nt].x, bh[nt].y);
            }
        }
    }

#pragma unroll
    for (int mi = 0; mi < 4; mi++) {
        if (mas[mi] < 0) continue;
        int ma = mas[mi], mb = ma + 8;
#pragma unroll
        for (int nt = 0; nt < 2; nt++) {
            int oc = (nq * 2 + nt) * 8 + t * 2;
            if (ma < 196) {
                sD[oc * 197 + ma] = acc[mi][nt][0];
                sD[(oc + 1) * 197 + ma] = acc[mi][nt][1];
            }
            if (mb < 196) {
                sD[oc * 197 + mb] = acc[mi][nt][2];
                sD[(oc + 1) * 197 + mb] = acc[mi][nt][3];
            }
        }
    }
    __syncthreads();

    // ---- pooled max/min + BN2 stat partials (4 threads per oc) ----
    if (tid < 256) {
        int oc = tid >> 2, h = tid & 3;
        float b = sbias[oc];
        const float* row = sD + oc * 197;
        float s = 0.f, q = 0.f;
        for (int p2 = h * 49; p2 < h * 49 + 49; p2++) {
            float v = row[p2] + b;
            s += v; q = fmaf(v, v, q);
        }
        s += __shfl_xor_sync(0xffffffffu, s, 1);
        q += __shfl_xor_sync(0xffffffffu, q, 1);
        s += __shfl_xor_sync(0xffffffffu, s, 2);
        q += __shfl_xor_sync(0xffffffffu, q, 2);
        if (h == 0) {
            g_part2[n * 128 + oc] = s;
            g_part2[n * 128 + 64 + oc] = q;
        }
        int w0 = h * 12, w1 = (h == 3) ? 49 : (h * 12 + 12);
        for (int ww = w0; ww < w1; ww++) {
            int wy = ww / 7, wx = ww - wy * 7;
            int pp = wy * 28 + 2 * wx;
            float u0 = row[pp] + b, u1 = row[pp + 1] + b;
            float u2 = row[pp + 14] + b, u3 = row[pp + 15] + b;
            int ob = (n * 64 + oc) * 49 + ww;
            g_o2max[ob] = fmaxf(fmaxf(u0, u1), fmaxf(u2, u3));
            g_o2min[ob] = fminf(fminf(u0, u1), fminf(u2, u3));
        }
    }
}

// ===== fc1 (BN2 select on pooled arrays; coalesced) =====
__global__ __launch_bounds__(256) void k_fc1(const float* __restrict__ fw)
{
    __shared__ float As[32][65], Bs[32][130];
    int m0 = blockIdx.x * 64, z = blockIdx.y;
    int kt0 = ((98 * z) / 8) * 32, kt1 = ((98 * (z + 1)) / 8) * 32;
    int tid = threadIdx.x, tx = tid & 31, ty = tid >> 5;
    float acc[8][4];
#pragma unroll
    for (int u = 0; u < 8; u++)
#pragma unroll
        for (int v = 0; v < 4; v++) acc[u][v] = 0.f;
    for (int k0 = kt0; k0 < kt1; k0 += 32) {
        for (int i = tid; i < 2048; i += 256) {
            int r = i >> 5, c = i & 31;
            int kk = k0 + c;
            int oc = kk / 49, p = kk - oc * 49;
            float sc = __ldg(&g_bn2[oc]), sh = __ldg(&g_bn2[64 + oc]);
            int off = ((m0 + r) * 64 + oc) * 49 + p;
            float base = (sc >= 0.f) ? g_o2max[off] : g_o2min[off];
            As[c][r] = fmaxf(fmaf(sc, base, sh), 0.f);
        }
        for (int i = tid; i < 4096; i += 256) {
            int r = i >> 5, c = i & 31;
            Bs[c][r] = fw[r * 3136 + k0 + c];
        }
        __syncthreads();
#pragma unroll
        for (int k = 0; k < 32; k++) {
            float a[8], b[4];
#pragma unroll
            for (int u = 0; u < 8; u++) a[u] = As[k][ty * 8 + u];
#pragma unroll
            for (int v = 0; v < 4; v++) b[v] = Bs[k][tx * 4 + v];
#pragma unroll
            for (int u = 0; u < 8; u++)
#pragma unroll
                for (int v = 0; v < 4; v++) acc[u][v] = fmaf(a[u], b[v], acc[u][v]);
        }
        __syncthreads();
    }
    float* pp = g_fcpart + z * (NB * 128);
#pragma unroll
    for (int u = 0; u < 8; u++)
#pragma unroll
        for (int v = 0; v < 4; v++)
            pp[(m0 + ty * 8 + u) * 128 + tx * 4 + v] = acc[u][v];
}

__global__ __launch_bounds__(256) void k_fc1combine(const float* __restrict__ fb)
{
    int idx = blockIdx.x * 256 + threadIdx.x;
    if (idx >= NB * 128) return;
    float v = fb[idx & 127];
#pragma unroll
    for (int z = 0; z < 8; z++) v += g_fcpart[z * (NB * 128) + idx];
    g_feat[idx] = fmaxf(v, 0.f);
}

// ===== SYRK chunk partials =====
__global__ __launch_bounds__(256) void k_syrk()
{
    __shared__ float As[64][33], Bs[64][33];
    int ti = blockIdx.x, tj = blockIdx.y, ch = blockIdx.z;
    int tid = threadIdx.x, tx = tid & 15, ty = tid >> 4, n0 = ch * 64;
    for (int i = tid; i < 2048; i += 256) {
        int r = i >> 5, c = i & 31;
        int gi = ti * 32 + c, gj = tj * 32 + c;
        As[r][c] = (gi < 128) ? g_feat[(n0 + r) * 128 + gi] : (gi == 128 ? 1.f : 0.f);
        Bs[r][c] = (gj < 128) ? g_feat[(n0 + r) * 128 + gj] : (gj == 128 ? 1.f : 0.f);
    }
    __syncthreads();
    float a00 = 0.f, a01 = 0.f, a10 = 0.f, a11 = 0.f;
#pragma unroll 8
    for (int k = 0; k < 64; k++) {
        float x0 = As[k][2 * ty], x1 = As[k][2 * ty + 1];
        float y0 = Bs[k][2 * tx], y1 = Bs[k][2 * tx + 1];
        a00 = fmaf(x0, y0, a00); a01 = fmaf(x0, y1, a01);
        a10 = fmaf(x1, y0, a10); a11 = fmaf(x1, y1, a11);
    }
    float* pa = g_partA + ch * 16641;
    int gi0 = ti * 32 + 2 * ty, gj0 = tj * 32 + 2 * tx;
    if (gi0 < 129 && gj0 < 129) pa[gi0 * 129 + gj0] = a00;
    if (gi0 < 129 && gj0 + 1 < 129) pa[gi0 * 129 + gj0 + 1] = a01;
    if (gi0 + 1 < 129 && gj0 < 129) pa[(gi0 + 1) * 129 + gj0] = a10;
    if (gi0 + 1 < 129 && gj0 + 1 < 129) pa[(gi0 + 1) * 129 + gj0 + 1] = a11;
}

__global__ __launch_bounds__(256) void k_reduceA()
{
    int o = blockIdx.x * 256 + threadIdx.x;
    if (o >= 16641) return;
    double s = ((o / 129) == (o % 129)) ? 1.0 : 0.0;
    for (int ch = 0; ch < 64; ch++) s += (double)g_partA[ch * 16641 + o];
    g_A[o] = s;
}

// ===== Phi^T Y chunk partials =====
__global__ __launch_bounds__(256) void k_phity(const float* __restrict__ y)
{
    __shared__ float sf[64 * 129], sy[640];
    int ch = blockIdx.x, n0 = ch * 64, tid = threadIdx.x;
    for (int i = tid; i < 8192; i += 256)
        sf[(i >> 7) * 129 + (i & 127)] = g_feat[(n0 + (i >> 7)) * 128 + (i & 127)];
    for (int i = tid; i < 64; i += 256) sf[i * 129 + 128] = 1.f;
    for (int i = tid; i < 640; i += 256) sy[i] = y[n0 * 10 + i];
    __syncthreads();
    for (int o = tid; o < 1290; o += 256) {
        int i = o / 10, c = o % 10;
        float s = 0.f;
        for (int r = 0; r < 64; r++) s = fmaf(sf[r * 129 + i], sy[r * 10 + c], s);
        g_partB[ch * 1290 + o] = s;
    }
}

__global__ __launch_bounds__(256) void k_Bfinal(const float* __restrict__ Wrls)
{
    int o = blockIdx.x * 256 + threadIdx.x;
    if (o >= 1290) return;
    double s = (double)Wrls[o];
    for (int ch = 0; ch < 64; ch++) s += (double)g_partB[ch * 1290 + o];
    g_Bm[o] = s;
}

// ===== fp64 Cholesky + 10-RHS solve (lower-triangle updates only) =====
__global__ __launch_bounds__(256) void k_chol(const float* __restrict__ Wrls,
                                              const int* __restrict__ sep)
{
    double* A = (double*)dynsmem;
    double* Bv = A + 129 * 130;
    int tid = threadIdx.x;
    if (sep[0] == 0) {
        for (int i = tid; i < 1290; i += 256) g_W[i] = Wrls[i];
        return;
    }
    for (int i = tid; i < 16641; i += 256) A[(i / 129) * 130 + (i % 129)] = g_A[i];
    for (int i = tid; i < 1290; i += 256) Bv[i] = g_Bm[i];
    __syncthreads();
    __shared__ double sinv;
    for (int k = 0; k < 129; k++) {
        if (tid == 0) {
            double d = sqrt(A[k * 130 + k]);
            A[k * 130 + k] = d;
            sinv = 1.0 / d;
        }
        __syncthreads();
        double iv = sinv;
        for (int i = k + 1 + tid; i < 129; i += 256) A[i * 130 + k] *= iv;
        __syncthreads();
        int m = 128 - k;
        for (int t = tid; t < m * m; t += 256) {
            int i = k + 1 + t / m, j = k + 1 + t % m;
            if (j <= i)
                A[i * 130 + j] -= A[i * 130 + k] * A[j * 130 + k];
        }
        __syncthreads();
    }
    for (int k = 0; k < 129; k++) {
        if (tid < 10) Bv[k * 10 + tid] /= A[k * 130 + k];
        __syncthreads();
        for (int t = tid; t < (128 - k) * 10; t += 256) {
            int i = k + 1 + t / 10, c = t % 10;
            Bv[i * 10 + c] -= A[i * 130 + k] * Bv[k * 10 + c];
        }
        __syncthreads();
    }
    for (int k = 128; k >= 0; k--) {
        if (tid < 10) Bv[k * 10 + tid] /= A[k * 130 + k];
        __syncthreads();
        for (int t = tid; t < k * 10; t += 256) {
            int i = t / 10, c = t % 10;
            Bv[i * 10 + c] -= A[k * 130 + i] * Bv[k * 10 + c];
        }
        __syncthreads();
    }
    for (int i = tid; i < 1290; i += 256) g_W[i] = (float)Bv[i];
}

// ===== head =====
__global__ __launch_bounds__(256) void k_head(float* __restrict__ out)
{
    __shared__ float sW[1290];
    int tid = threadIdx.x;
    for (int i = tid; i < 1290; i += 256) sW[i] = g_W[i];
    __syncthreads();
    int idx = blockIdx.x * 256 + tid;
    if (idx >= NB * 10) return;
    int n = idx / 10, c = idx % 10;
    float acc = sW[1280 + c];
    const float* f = g_feat + n * 128;
#pragma unroll 8
    for (int i = 0; i < 128; i++) acc = fmaf(f[i], sW[i * 10 + c], acc);
    out[idx] = acc;
}

extern "C" void kernel_launch(void* const* d_in, const int* in_sizes, int n_in,
                              void* d_out, int out_size)
{
    const float* x       = (const float*)d_in[0];
    const float* y       = (const float*)d_in[1];
    const float* conv1_w = (const float*)d_in[2];
    const float* conv1_b = (const float*)d_in[3];
    const float* bn1_g   = (const float*)d_in[4];
    const float* bn1_b   = (const float*)d_in[5];
    const float* conv2_w = (const float*)d_in[6];
    const float* conv2_b = (const float*)d_in[7];
    const float* bn2_g   = (const float*)d_in[8];
    const float* bn2_b   = (const float*)d_in[9];
    const float* fc1_w   = (const float*)d_in[10];
    const float* fc1_b   = (const float*)d_in[11];
    const float* W_rls   = (const float*)d_in[12];
    const int*   sep     = (const int*)d_in[14];
    float* out = (float*)d_out;

    cudaFuncSetAttribute(k_conv2_mma, cudaFuncAttributeMaxDynamicSharedMemorySize, C2M_SMEM);
    cudaFuncSetAttribute(k_chol, cudaFuncAttributeMaxDynamicSharedMemorySize, 144480);

    float* p1; cudaGetSymbolAddress((void**)&p1, g_part1);
    float* p2; cudaGetSymbolAddress((void**)&p2, g_part2);
    float* b1; cudaGetSymbolAddress((void**)&b1, g_bn1);
    float* b2; cudaGetSymbolAddress((void**)&b2, g_bn2);

    k_prepw<<<86, 256>>>(conv2_w);
    k_conv1_mmx<<<NB, 224>>>(x, conv1_w, conv1_b);
    k_bnfinal<<<32, 256>>>(bn1_g, bn1_b, p1, b1, 32, 1.f / (float)(NB * 784));
    k_conv2_mma<<<NB, 512, C2M_SMEM>>>(conv2_b);
    k_bnfinal<<<64, 256>>>(bn2_g, bn2_b, p2, b2, 64, 1.f / (float)(NB * 196));
    k_fc1<<<dim3(64, 8), 256>>>(fc1_w);
    k_fc1combine<<<(NB * 128) / 256, 256>>>(fc1_b);
    k_syrk<<<dim3(5, 5, 64), 256>>>();
    k_reduceA<<<66, 256>>>();
    k_phity<<<64, 256>>>(y);
    k_Bfinal<<<6, 256>>>(W_rls);
    k_chol<<<1, 256, 144480>>>(W_rls, sep);
    k_head<<<(NB * 10 + 255) / 256, 256>>>(out);
}

// round 14
// speedup vs baseline: 1.0229x; 1.0229x over previous
#include <cuda_runtime.h>
#include <cuda_bf16.h>
#include <math.h>
#include <cstdint>

#define NB 4096

// ----- scratch (device globals; no allocations) -----
__device__ float  g_h1max[NB * 32 * 196];
__device__ float  g_h1min[NB * 32 * 196];
__device__ float  g_o2max[NB * 64 * 49];
__device__ float  g_o2min[NB * 64 * 49];
__device__ float  g_feat[NB * 128];
__device__ float  g_part1[NB * 64];
__device__ float  g_part2[NB * 128];
__device__ float  g_bn1[64];
__device__ float  g_bn2[128];
__device__ float  g_fcpart[8 * NB * 128];
__device__ float  g_partA[64 * 129 * 129];
__device__ float  g_partB[64 * 1290];
__device__ double g_A[129 * 129];
__device__ double g_Bm[1290];
__device__ float  g_W[1290];
__device__ uint32_t g_Wfh[21888];      // 72 krows x 76 (padded) x uint2
__device__ uint32_t g_Wfl[21888];

extern __shared__ char dynsmem[];

__device__ __forceinline__ void mma_bf16(float* c, uint32_t a0, uint32_t a1,
                                         uint32_t a2, uint32_t a3,
                                         uint32_t b0, uint32_t b1)
{
    asm volatile(
        "mma.sync.aligned.m16n8k16.row.col.f32.bf16.bf16.f32 "
        "{%0,%1,%2,%3}, {%4,%5,%6,%7}, {%8,%9}, {%0,%1,%2,%3};"
        : "+f"(c[0]), "+f"(c[1]), "+f"(c[2]), "+f"(c[3])
        : "r"(a0), "r"(a1), "r"(a2), "r"(a3), "r"(b0), "r"(b1));
}

__device__ __forceinline__ uint32_t packbf(float v0, float v1)
{
    __nv_bfloat162 p = __floats2bfloat162_rn(v0, v1);
    return *(uint32_t*)&p;
}

// ===== conv1 single pass: raw-conv window max/min + BN stats =====
__global__ __launch_bounds__(224) void k_conv1_mmx(
    const float* __restrict__ x, const float* __restrict__ w, const float* __restrict__ bias)
{
    __shared__ float simg[900], sw[288], sb[32], wred[7][64];
    int n = blockIdx.x, tid = threadIdx.x;
    for (int i = tid; i < 900; i += 224) simg[i] = 0.f;
    for (int i = tid; i < 288; i += 224) sw[i] = w[i];
    if (tid < 32) sb[tid] = bias[tid];
    __syncthreads();
    const float* xi = x + n * 784;
    for (int i = tid; i < 784; i += 224)
        simg[(i / 28 + 1) * 30 + (i % 28) + 1] = xi[i];
    __syncthreads();

    float ls[32], lq[32];
#pragma unroll
    for (int c = 0; c < 32; c++) { ls[c] = 0.f; lq[c] = 0.f; }

    if (tid < 196) {
        int py = tid / 14, px = tid % 14;
        float patch[16];
#pragma unroll
        for (int dy = 0; dy < 4; dy++)
#pragma unroll
            for (int dx = 0; dx < 4; dx++)
                patch[dy * 4 + dx] = simg[(2 * py + dy) * 30 + 2 * px + dx];
#pragma unroll
        for (int oc = 0; oc < 32; oc++) {
            float v[4];
#pragma unroll
            for (int dy = 0; dy < 2; dy++)
#pragma unroll
                for (int dx = 0; dx < 2; dx++) {
                    float a = sb[oc];
#pragma unroll
                    for (int ky = 0; ky < 3; ky++)
#pragma unroll
                        for (int kx = 0; kx < 3; kx++)
                            a = fmaf(sw[oc * 9 + ky * 3 + kx],
                                     patch[(dy + ky) * 4 + dx + kx], a);
                    v[dy * 2 + dx] = a;
                }
            float mx = fmaxf(fmaxf(v[0], v[1]), fmaxf(v[2], v[3]));
            float mn = fminf(fminf(v[0], v[1]), fminf(v[2], v[3]));
            g_h1max[(n * 32 + oc) * 196 + tid] = mx;
            g_h1min[(n * 32 + oc) * 196 + tid] = mn;
            ls[oc] += (v[0] + v[1]) + (v[2] + v[3]);
            lq[oc] = fmaf(v[0], v[0], fmaf(v[1], v[1], fmaf(v[2], v[2], fmaf(v[3], v[3], lq[oc]))));
        }
    }
    int lane = tid & 31, wid = tid >> 5;
#pragma unroll
    for (int oc = 0; oc < 32; oc++) {
        float s = ls[oc], q = lq[oc];
#pragma unroll
        for (int o = 16; o > 0; o >>= 1) {
            s += __shfl_down_sync(0xffffffffu, s, o);
            q += __shfl_down_sync(0xffffffffu, q, o);
        }
        if (lane == 0) { wred[wid][oc] = s; wred[wid][32 + oc] = q; }
    }
    __syncthreads();
    if (tid < 64) {
        float s = 0.f;
#pragma unroll
        for (int w7 = 0; w7 < 7; w7++) s += wred[w7][tid];
        g_part1[n * 64 + tid] = s;
    }
}

// ===== BN finalize =====
__global__ __launch_bounds__(256) void k_bnfinal(
    const float* __restrict__ gamma, const float* __restrict__ beta,
    const float* __restrict__ part, float* __restrict__ bn, int nc, float invN)
{
    int c = blockIdx.x, tid = threadIdx.x;
    float s = 0.f, q = 0.f;
    for (int r = tid; r < NB; r += 256) {
        s += part[r * 2 * nc + c];
        q += part[r * 2 * nc + nc + c];
    }
    __shared__ float ss[256], sq[256];
    ss[tid] = s; sq[tid] = q; __syncthreads();
    for (int o = 128; o > 0; o >>= 1) {
        if (tid < o) { ss[tid] += ss[tid + o]; sq[tid] += sq[tid + o]; }
        __syncthreads();
    }
    if (tid == 0) {
        float mean = ss[0] * invN;
        float var = sq[0] * invN - mean * mean;
        float scale = gamma[c] * rsqrtf(var + 1e-5f);
        bn[c] = scale;
        bn[nc + c] = beta[c] - mean * scale;
    }
}

// ===== weight fragment prep (once): pair-packed hi/lo, PADDED stride 76 =====
__global__ __launch_bounds__(256) void k_prepw(const float* __restrict__ cw)
{
    int i = blockIdx.x * 256 + threadIdx.x;
    if (i >= 21888) return;
    int pair = i >> 1, u = i & 1;
    int krow = pair / 76, nb = pair % 76;
    int kt = krow >> 2, t = krow & 3;
    uint32_t hw = 0, lw = 0;
    if (nb < 64) {
        int srow = kt * 8 + t + 4 * u;
        int s9 = srow >> 4, j = srow & 15;
        float w0 = cw[nb * 288 + 2 * j * 9 + s9];
        float w1 = cw[nb * 288 + (2 * j + 1) * 9 + s9];
        __nv_bfloat16 h0 = __float2bfloat16_rn(w0);
        __nv_bfloat16 h1 = __float2bfloat16_rn(w1);
        __nv_bfloat162 hp; hp.x = h0; hp.y = h1;
        hw = *(uint32_t*)&hp;
        lw = packbf(w0 - __bfloat162float(h0), w1 - __bfloat162float(h1));
    }
    g_Wfh[i] = hw;
    g_Wfl[i] = lw;
}

// ===================== conv2 via mma.sync bf16 split (HMMA), v6 =====================
// 16 warps = 8 mg x 2 nq; per warp: <=2 m-tiles x 4 n-tiles.
// A: uint2, row stride 13 (26 words, conflict-free). B: stride 76 (conflict-free).
// smem: Tah 0 (29952), Tal 29952, Wfh 59904 (43776), Wfl 103680, sD 147456 (50432).
// total 197888.
#define C2M_SMEM 197888

__global__ __launch_bounds__(512, 1) void k_conv2_mma(const float* __restrict__ cb)
{
    uint2* Tah = (uint2*)dynsmem;                    // [288 rows][13]
    uint2* Tal = (uint2*)(dynsmem + 29952);
    uint2* Wfh = (uint2*)(dynsmem + 59904);          // [72 krows][76]
    uint2* Wfl = (uint2*)(dynsmem + 103680);
    float* sD  = (float*)(dynsmem + 147456);         // [64][197]
    __shared__ float ssc1[32], ssh1[32], sbias[64];

    int n = blockIdx.x, tid = threadIdx.x;
    int lane = tid & 31, w = tid >> 5;
    int g = lane >> 2, t = lane & 3;

    if (tid < 32) { ssc1[tid] = g_bn1[tid]; ssh1[tid] = g_bn1[32 + tid]; }
    if (tid < 64) sbias[tid] = cb[tid];

    {
        const uint2* gh = (const uint2*)g_Wfh;
        const uint2* gl = (const uint2*)g_Wfl;
        for (int i = tid; i < 5472; i += 512) { Wfh[i] = gh[i]; Wfl[i] = gl[i]; }
    }
    for (int i = tid; i < 3744; i += 512) {
        Tah[i] = make_uint2(0u, 0u);
        Tal[i] = make_uint2(0u, 0u);
    }
    __syncthreads();

    // input: BN1 select + relu, split hi/lo into pair-packed layout (stride 13 uint2)
    const float* mxp = g_h1max + n * 6272;
    const float* mnp = g_h1min + n * 6272;
    __nv_bfloat16* Th16 = (__nv_bfloat16*)Tah;
    __nv_bfloat16* Tl16 = (__nv_bfloat16*)Tal;
    for (int i = tid; i < 6272; i += 512) {
        int ci = i / 196, p = i % 196;
        float sc = ssc1[ci], sh = ssh1[ci];
        float base = (sc >= 0.f) ? mxp[i] : mnp[i];
        float v = fmaxf(fmaf(sc, base, sh), 0.f);
        __nv_bfloat16 hbf = __float2bfloat16_rn(v);
        float lf = v - __bfloat162float(hbf);
        int j = ci >> 1, hh = j >> 3, r = j & 7;
        int tt = r & 3, u = r >> 2;
        int row = (p / 14 + 1) * 16 + (p % 14 + 1);
        int word = row * 26 + (hh * 4 + tt) * 2 + u;   // 32-bit word index
        Th16[word * 2 + (ci & 1)] = hbf;
        Tl16[word * 2 + (ci & 1)] = __float2bfloat16_rn(lf);
    }
    __syncthreads();

    // warp = (mg, nq): mg owns m-tiles {mg, mg+8} (dummy replays mg), nq owns n-tiles nq*4..+3
    int mg = w & 7, nq = w >> 3;
    int pixa[2], pixb[2], mas[2];
#pragma unroll
    for (int mi = 0; mi < 2; mi++) {
        int mt = mg + 8 * mi;
        bool real = mt < 13;
        int mt2 = real ? mt : mg;
        int ma = mt2 * 16 + g;
        int mb = ma + 8;
        mas[mi] = real ? ma : -1;
        pixa[mi] = ((ma / 14) * 16 + (ma % 14)) * 13;
        pixb[mi] = ((mb / 14) * 16 + (mb % 14)) * 13;
    }
    float acc[2][4][4];
#pragma unroll
    for (int mi = 0; mi < 2; mi++)
#pragma unroll
        for (int nt = 0; nt < 4; nt++)
#pragma unroll
            for (int c = 0; c < 4; c++) acc[mi][nt][c] = 0.f;

    int nb0 = nq * 32 + g;

#pragma unroll 9
    for (int kt = 0; kt < 18; kt++) {
        int s = kt >> 1, hh = kt & 1;
        int off13 = ((s / 3) * 16 + (s % 3)) * 13;
        int wbase = (kt * 4 + t) * 76 + nb0;
        uint2 bh[4], bl[4];
#pragma unroll
        for (int nt = 0; nt < 4; nt++) {
            bh[nt] = Wfh[wbase + nt * 8];
            bl[nt] = Wfl[wbase + nt * 8];
        }
        int abase = off13 + hh * 4 + t;
#pragma unroll
        for (int mi = 0; mi < 2; mi++) {
            uint2 uah = Tah[pixa[mi] + abase];
            uint2 ubh = Tah[pixb[mi] + abase];
            uint2 ual = Tal[pixa[mi] + abase];
            uint2 ubl = Tal[pixb[mi] + abase];
#pragma unroll
            for (int nt = 0; nt < 4; nt++) {
                mma_bf16(acc[mi][nt], uah.x, ubh.x, uah.y, ubh.y, bh[nt].x, bh[nt].y);
                mma_bf16(acc[mi][nt], uah.x, ubh.x, uah.y, ubh.y, bl[nt].x, bl[nt].y);
                mma_bf16(acc[mi][nt], ual.x, ubl.x, ual.y, ubl.y, bh[nt].x, bh[nt].y);
            }
        }
    }

#pragma unroll
    for (int mi = 0; mi < 2; mi++) {
        if (mas[mi] < 0) continue;
        int ma = mas[mi], mb = ma + 8;
#pragma unroll
        for (int nt = 0; nt < 4; nt++) {
            int oc = (nq * 4 + nt) * 8 + t * 2;
            if (ma < 196) {
                sD[oc * 197 + ma] = acc[mi][nt][0];
                sD[(oc + 1) * 197 + ma] = acc[mi][nt][1];
            }
            if (mb < 196) {
                sD[oc * 197 + mb] = acc[mi][nt][2];
                sD[(oc + 1) * 197 + mb] = acc[mi][nt][3];
            }
        }
    }
    __syncthreads();

    // ---- pooled max/min + BN2 stat partials (4 threads per oc) ----
    if (tid < 256) {
        int oc = tid >> 2, h = tid & 3;
        float b = sbias[oc];
        const float* row = sD + oc * 197;
        float s = 0.f, q = 0.f;
        for (int p2 = h * 49; p2 < h * 49 + 49; p2++) {
            float v = row[p2] + b;
            s += v; q = fmaf(v, v, q);
        }
        s += __shfl_xor_sync(0xffffffffu, s, 1);
        q += __shfl_xor_sync(0xffffffffu, q, 1);
        s += __shfl_xor_sync(0xffffffffu, s, 2);
        q += __shfl_xor_sync(0xffffffffu, q, 2);
        if (h == 0) {
            g_part2[n * 128 + oc] = s;
            g_part2[n * 128 + 64 + oc] = q;
        }
        int w0 = h * 12, w1 = (h == 3) ? 49 : (h * 12 + 12);
        for (int ww = w0; ww < w1; ww++) {
            int wy = ww / 7, wx = ww - wy * 7;
            int pp = wy * 28 + 2 * wx;
            float u0 = row[pp] + b, u1 = row[pp + 1] + b;
            float u2 = row[pp + 14] + b, u3 = row[pp + 15] + b;
            int ob = (n * 64 + oc) * 49 + ww;
            g_o2max[ob] = fmaxf(fmaxf(u0, u1), fmaxf(u2, u3));
            g_o2min[ob] = fminf(fminf(u0, u1), fminf(u2, u3));
        }
    }
}

// ===== fc1 (BN2 select on pooled arrays; coalesced) =====
__global__ __launch_bounds__(256) void k_fc1(const float* __restrict__ fw)
{
    __shared__ float As[32][65], Bs[32][130];
    int m0 = blockIdx.x * 64, z = blockIdx.y;
    int kt0 = ((98 * z) / 8) * 32, kt1 = ((98 * (z + 1)) / 8) * 32;
    int tid = threadIdx.x, tx = tid & 31, ty = tid >> 5;
    float acc[8][4];
#pragma unroll
    for (int u = 0; u < 8; u++)
#pragma unroll
        for (int v = 0; v < 4; v++) acc[u][v] = 0.f;
    for (int k0 = kt0; k0 < kt1; k0 += 32) {
        for (int i = tid; i < 2048; i += 256) {
            int r = i >> 5, c = i & 31;
            int kk = k0 + c;
            int oc = kk / 49, p = kk - oc * 49;
            float sc = __ldg(&g_bn2[oc]), sh = __ldg(&g_bn2[64 + oc]);
            int off = ((m0 + r) * 64 + oc) * 49 + p;
            float base = (sc >= 0.f) ? g_o2max[off] : g_o2min[off];
            As[c][r] = fmaxf(fmaf(sc, base, sh), 0.f);
        }
        for (int i = tid; i < 4096; i += 256) {
            int r = i >> 5, c = i & 31;
            Bs[c][r] = fw[r * 3136 + k0 + c];
        }
        __syncthreads();
#pragma unroll
        for (int k = 0; k < 32; k++) {
            float a[8], b[4];
#pragma unroll
            for (int u = 0; u < 8; u++) a[u] = As[k][ty * 8 + u];
#pragma unroll
            for (int v = 0; v < 4; v++) b[v] = Bs[k][tx * 4 + v];
#pragma unroll
            for (int u = 0; u < 8; u++)
#pragma unroll
                for (int v = 0; v < 4; v++) acc[u][v] = fmaf(a[u], b[v], acc[u][v]);
        }
        __syncthreads();
    }
    float* pp = g_fcpart + z * (NB * 128);
#pragma unroll
    for (int u = 0; u < 8; u++)
#pragma unroll
        for (int v = 0; v < 4; v++)
            pp[(m0 + ty * 8 + u) * 128 + tx * 4 + v] = acc[u][v];
}

__global__ __launch_bounds__(256) void k_fc1combine(const float* __restrict__ fb)
{
    int idx = blockIdx.x * 256 + threadIdx.x;
    if (idx >= NB * 128) return;
    float v = fb[idx & 127];
#pragma unroll
    for (int z = 0; z < 8; z++) v += g_fcpart[z * (NB * 128) + idx];
    g_feat[idx] = fmaxf(v, 0.f);
}

// ===== SYRK chunk partials =====
__global__ __launch_bounds__(256) void k_syrk()
{
    __shared__ float As[64][33], Bs[64][33];
    int ti = blockIdx.x, tj = blockIdx.y, ch = blockIdx.z;
    int tid = threadIdx.x, tx = tid & 15, ty = tid >> 4, n0 = ch * 64;
    for (int i = tid; i < 2048; i += 256) {
        int r = i >> 5, c = i & 31;
        int gi = ti * 32 + c, gj = tj * 32 + c;
        As[r][c] = (gi < 128) ? g_feat[(n0 + r) * 128 + gi] : (gi == 128 ? 1.f : 0.f);
        Bs[r][c] = (gj < 128) ? g_feat[(n0 + r) * 128 + gj] : (gj == 128 ? 1.f : 0.f);
    }
    __syncthreads();
    float a00 = 0.f, a01 = 0.f, a10 = 0.f, a11 = 0.f;
#pragma unroll 8
    for (int k = 0; k < 64; k++) {
        float x0 = As[k][2 * ty], x1 = As[k][2 * ty + 1];
        float y0 = Bs[k][2 * tx], y1 = Bs[k][2 * tx + 1];
        a00 = fmaf(x0, y0, a00); a01 = fmaf(x0, y1, a01);
        a10 = fmaf(x1, y0, a10); a11 = fmaf(x1, y1, a11);
    }
    float* pa = g_partA + ch * 16641;
    int gi0 = ti * 32 + 2 * ty, gj0 = tj * 32 + 2 * tx;
    if (gi0 < 129 && gj0 < 129) pa[gi0 * 129 + gj0] = a00;
    if (gi0 < 129 && gj0 + 1 < 129) pa[gi0 * 129 + gj0 + 1] = a01;
    if (gi0 + 1 < 129 && gj0 < 129) pa[(gi0 + 1) * 129 + gj0] = a10;
    if (gi0 + 1 < 129 && gj0 + 1 < 129) pa[(gi0 + 1) * 129 + gj0 + 1] = a11;
}

__global__ __launch_bounds__(256) void k_reduceA()
{
    int o = blockIdx.x * 256 + threadIdx.x;
    if (o >= 16641) return;
    double s = ((o / 129) == (o % 129)) ? 1.0 : 0.0;
    for (int ch = 0; ch < 64; ch++) s += (double)g_partA[ch * 16641 + o];
    g_A[o] = s;
}

// ===== Phi^T Y chunk partials =====
__global__ __launch_bounds__(256) void k_phity(const float* __restrict__ y)
{
    __shared__ float sf[64 * 129], sy[640];
    int ch = blockIdx.x, n0 = ch * 64, tid = threadIdx.x;
    for (int i = tid; i < 8192; i += 256)
        sf[(i >> 7) * 129 + (i & 127)] = g_feat[(n0 + (i >> 7)) * 128 + (i & 127)];
    for (int i = tid; i < 64; i += 256) sf[i * 129 + 128] = 1.f;
    for (int i = tid; i < 640; i += 256) sy[i] = y[n0 * 10 + i];
    __syncthreads();
    for (int o = tid; o < 1290; o += 256) {
        int i = o / 10, c = o % 10;
        float s = 0.f;
        for (int r = 0; r < 64; r++) s = fmaf(sf[r * 129 + i], sy[r * 10 + c], s);
        g_partB[ch * 1290 + o] = s;
    }
}

__global__ __launch_bounds__(256) void k_Bfinal(const float* __restrict__ Wrls)
{
    int o = blockIdx.x * 256 + threadIdx.x;
    if (o >= 1290) return;
    double s = (double)Wrls[o];
    for (int ch = 0; ch < 64; ch++) s += (double)g_partB[ch * 1290 + o];
    g_Bm[o] = s;
}

// ===== fp64 Cholesky + 10-RHS solve (lower-triangle updates only) =====
__global__ __launch_bounds__(256) void k_chol(const float* __restrict__ Wrls,
                                              const int* __restrict__ sep)
{
    double* A = (double*)dynsmem;
    double* Bv = A + 129 * 130;
    int tid = threadIdx.x;
    if (sep[0] == 0) {
        for (int i = tid; i < 1290; i += 256) g_W[i] = Wrls[i];
        return;
    }
    for (int i = tid; i < 16641; i += 256) A[(i / 129) * 130 + (i % 129)] = g_A[i];
    for (int i = tid; i < 1290; i += 256) Bv[i] = g_Bm[i];
    __syncthreads();
    __shared__ double sinv;
    for (int k = 0; k < 129; k++) {
        if (tid == 0) {
            double d = sqrt(A[k * 130 + k]);
            A[k * 130 + k] = d;
            sinv = 1.0 / d;
        }
        __syncthreads();
        double iv = sinv;
        for (int i = k + 1 + tid; i < 129; i += 256) A[i * 130 + k] *= iv;
        __syncthreads();
        int m = 128 - k;
        for (int t = tid; t < m * m; t += 256) {
            int i = k + 1 + t / m, j = k + 1 + t % m;
            if (j <= i)
                A[i * 130 + j] -= A[i * 130 + k] * A[j * 130 + k];
        }
        __syncthreads();
    }
    for (int k = 0; k < 129; k++) {
        if (tid < 10) Bv[k * 10 + tid] /= A[k * 130 + k];
        __syncthreads();
        for (int t = tid; t < (128 - k) * 10; t += 256) {
            int i = k + 1 + t / 10, c = t % 10;
            Bv[i * 10 + c] -= A[i * 130 + k] * Bv[k * 10 + c];
        }
        __syncthreads();
    }
    for (int k = 128; k >= 0; k--) {
        if (tid < 10) Bv[k * 10 + tid] /= A[k * 130 + k];
        __syncthreads();
        for (int t = tid; t < k * 10; t += 256) {
            int i = t / 10, c = t % 10;
            Bv[i * 10 + c] -= A[k * 130 + i] * Bv[k * 10 + c];
        }
        __syncthreads();
    }
    for (int i = tid; i < 1290; i += 256) g_W[i] = (float)Bv[i];
}

// ===== head =====
__global__ __launch_bounds__(256) void k_head(float* __restrict__ out)
{
    __shared__ float sW[1290];
    int tid = threadIdx.x;
    for (int i = tid; i < 1290; i += 256) sW[i] = g_W[i];
    __syncthreads();
    int idx = blockIdx.x * 256 + tid;
    if (idx >= NB * 10) return;
    int n = idx / 10, c = idx % 10;
    float acc = sW[1280 + c];
    const float* f = g_feat + n * 128;
#pragma unroll 8
    for (int i = 0; i < 128; i++) acc = fmaf(f[i], sW[i * 10 + c], acc);
    out[idx] = acc;
}

extern "C" void kernel_launch(void* const* d_in, const int* in_sizes, int n_in,
                              void* d_out, int out_size)
{
    const float* x       = (const float*)d_in[0];
    const float* y       = (const float*)d_in[1];
    const float* conv1_w = (const float*)d_in[2];
    const float* conv1_b = (const float*)d_in[3];
    const float* bn1_g   = (const float*)d_in[4];
    const float* bn1_b   = (const float*)d_in[5];
    const float* conv2_w = (const float*)d_in[6];
    const float* conv2_b = (const float*)d_in[7];
    const float* bn2_g   = (const float*)d_in[8];
    const float* bn2_b   = (const float*)d_in[9];
    const float* fc1_w   = (const float*)d_in[10];
    const float* fc1_b   = (const float*)d_in[11];
    const float* W_rls   = (const float*)d_in[12];
    const int*   sep     = (const int*)d_in[14];
    float* out = (float*)d_out;

    cudaFuncSetAttribute(k_conv2_mma, cudaFuncAttributeMaxDynamicSharedMemorySize, C2M_SMEM);
    cudaFuncSetAttribute(k_chol, cudaFuncAttributeMaxDynamicSharedMemorySize, 144480);

    float* p1; cudaGetSymbolAddress((void**)&p1, g_part1);
    float* p2; cudaGetSymbolAddress((void**)&p2, g_part2);
    float* b1; cudaGetSymbolAddress((void**)&b1, g_bn1);
    float* b2; cudaGetSymbolAddress((void**)&b2, g_bn2);

    k_prepw<<<86, 256>>>(conv2_w);
    k_conv1_mmx<<<NB, 224>>>(x, conv1_w, conv1_b);
    k_bnfinal<<<32, 256>>>(bn1_g, bn1_b, p1, b1, 32, 1.f / (float)(NB * 784));
    k_conv2_mma<<<NB, 512, C2M_SMEM>>>(conv2_b);
    k_bnfinal<<<64, 256>>>(bn2_g, bn2_b, p2, b2, 64, 1.f / (float)(NB * 196));
    k_fc1<<<dim3(64, 8), 256>>>(fc1_w);
    k_fc1combine<<<(NB * 128) / 256, 256>>>(fc1_b);
    k_syrk<<<dim3(5, 5, 64), 256>>>();
    k_reduceA<<<66, 256>>>();
    k_phity<<<64, 256>>>(y);
    k_Bfinal<<<6, 256>>>(W_rls);
    k_chol<<<1, 256, 144480>>>(W_rls, sep);
    k_head<<<(NB * 10 + 255) / 256, 256>>>(out);
}

// round 15
// speedup vs baseline: 1.1216x; 1.0965x over previous
#include <cuda_runtime.h>
#include <cuda_bf16.h>
#include <math.h>
#include <cstdint>

#define NB 4096

// ----- scratch (device globals; no allocations) -----
__device__ float  g_h1max[NB * 32 * 196];
__device__ float  g_h1min[NB * 32 * 196];
__device__ float  g_o2max[NB * 64 * 49];
__device__ float  g_o2min[NB * 64 * 49];
__device__ float  g_feat[NB * 128];
__device__ float  g_part1[NB * 64];
__device__ float  g_part2[NB * 128];
__device__ float  g_bn1[64];
__device__ float  g_bn2[128];
__device__ float  g_fcpart[8 * NB * 128];
__device__ float  g_partA[64 * 129 * 129];
__device__ float  g_partB[64 * 1290];
__device__ double g_A[129 * 129];
__device__ double g_Bm[1290];
__device__ float  g_W[1290];
__device__ uint32_t g_Wfh[21888];      // 72 krows x 76 (padded) x uint2
__device__ uint32_t g_Wfl[21888];

extern __shared__ char dynsmem[];

__device__ __forceinline__ void mma_bf16(float* c, uint32_t a0, uint32_t a1,
                                         uint32_t a2, uint32_t a3,
                                         uint32_t b0, uint32_t b1)
{
    asm volatile(
        "mma.sync.aligned.m16n8k16.row.col.f32.bf16.bf16.f32 "
        "{%0,%1,%2,%3}, {%4,%5,%6,%7}, {%8,%9}, {%0,%1,%2,%3};"
        : "+f"(c[0]), "+f"(c[1]), "+f"(c[2]), "+f"(c[3])
        : "r"(a0), "r"(a1), "r"(a2), "r"(a3), "r"(b0), "r"(b1));
}

__device__ __forceinline__ uint32_t packbf(float v0, float v1)
{
    __nv_bfloat162 p = __floats2bfloat162_rn(v0, v1);
    return *(uint32_t*)&p;
}

// ===== conv1 single pass: raw-conv window max/min + BN stats =====
__global__ __launch_bounds__(224) void k_conv1_mmx(
    const float* __restrict__ x, const float* __restrict__ w, const float* __restrict__ bias)
{
    __shared__ float simg[900], sw[288], sb[32], wred[7][64];
    int n = blockIdx.x, tid = threadIdx.x;
    for (int i = tid; i < 900; i += 224) simg[i] = 0.f;
    for (int i = tid; i < 288; i += 224) sw[i] = w[i];
    if (tid < 32) sb[tid] = bias[tid];
    __syncthreads();
    const float* xi = x + n * 784;
    for (int i = tid; i < 784; i += 224)
        simg[(i / 28 + 1) * 30 + (i % 28) + 1] = xi[i];
    __syncthreads();

    float ls[32], lq[32];
#pragma unroll
    for (int c = 0; c < 32; c++) { ls[c] = 0.f; lq[c] = 0.f; }

    if (tid < 196) {
        int py = tid / 14, px = tid % 14;
        float patch[16];
#pragma unroll
        for (int dy = 0; dy < 4; dy++)
#pragma unroll
            for (int dx = 0; dx < 4; dx++)
                patch[dy * 4 + dx] = simg[(2 * py + dy) * 30 + 2 * px + dx];
#pragma unroll
        for (int oc = 0; oc < 32; oc++) {
            float v[4];
#pragma unroll
            for (int dy = 0; dy < 2; dy++)
#pragma unroll
                for (int dx = 0; dx < 2; dx++) {
                    float a = sb[oc];
#pragma unroll
                    for (int ky = 0; ky < 3; ky++)
#pragma unroll
                        for (int kx = 0; kx < 3; kx++)
                            a = fmaf(sw[oc * 9 + ky * 3 + kx],
                                     patch[(dy + ky) * 4 + dx + kx], a);
                    v[dy * 2 + dx] = a;
                }
            float mx = fmaxf(fmaxf(v[0], v[1]), fmaxf(v[2], v[3]));
            float mn = fminf(fminf(v[0], v[1]), fminf(v[2], v[3]));
            g_h1max[(n * 32 + oc) * 196 + tid] = mx;
            g_h1min[(n * 32 + oc) * 196 + tid] = mn;
            ls[oc] += (v[0] + v[1]) + (v[2] + v[3]);
            lq[oc] = fmaf(v[0], v[0], fmaf(v[1], v[1], fmaf(v[2], v[2], fmaf(v[3], v[3], lq[oc]))));
        }
    }
    int lane = tid & 31, wid = tid >> 5;
#pragma unroll
    for (int oc = 0; oc < 32; oc++) {
        float s = ls[oc], q = lq[oc];
#pragma unroll
        for (int o = 16; o > 0; o >>= 1) {
            s += __shfl_down_sync(0xffffffffu, s, o);
            q += __shfl_down_sync(0xffffffffu, q, o);
        }
        if (lane == 0) { wred[wid][oc] = s; wred[wid][32 + oc] = q; }
    }
    __syncthreads();
    if (tid < 64) {
        float s = 0.f;
#pragma unroll
        for (int w7 = 0; w7 < 7; w7++) s += wred[w7][tid];
        g_part1[n * 64 + tid] = s;
    }
}

// ===== BN finalize =====
__global__ __launch_bounds__(256) void k_bnfinal(
    const float* __restrict__ gamma, const float* __restrict__ beta,
    const float* __restrict__ part, float* __restrict__ bn, int nc, float invN)
{
    int c = blockIdx.x, tid = threadIdx.x;
    float s = 0.f, q = 0.f;
    for (int r = tid; r < NB; r += 256) {
        s += part[r * 2 * nc + c];
        q += part[r * 2 * nc + nc + c];
    }
    __shared__ float ss[256], sq[256];
    ss[tid] = s; sq[tid] = q; __syncthreads();
    for (int o = 128; o > 0; o >>= 1) {
        if (tid < o) { ss[tid] += ss[tid + o]; sq[tid] += sq[tid + o]; }
        __syncthreads();
    }
    if (tid == 0) {
        float mean = ss[0] * invN;
        float var = sq[0] * invN - mean * mean;
        float scale = gamma[c] * rsqrtf(var + 1e-5f);
        bn[c] = scale;
        bn[nc + c] = beta[c] - mean * scale;
    }
}

// ===== weight fragment prep (once): pair-packed hi/lo, PADDED stride 76 =====
__global__ __launch_bounds__(256) void k_prepw(const float* __restrict__ cw)
{
    int i = blockIdx.x * 256 + threadIdx.x;
    if (i >= 21888) return;
    int pair = i >> 1, u = i & 1;
    int krow = pair / 76, nb = pair % 76;
    int kt = krow >> 2, t = krow & 3;
    uint32_t hw = 0, lw = 0;
    if (nb < 64) {
        int srow = kt * 8 + t + 4 * u;
        int s9 = srow >> 4, j = srow & 15;
        float w0 = cw[nb * 288 + 2 * j * 9 + s9];
        float w1 = cw[nb * 288 + (2 * j + 1) * 9 + s9];
        __nv_bfloat16 h0 = __float2bfloat16_rn(w0);
        __nv_bfloat16 h1 = __float2bfloat16_rn(w1);
        __nv_bfloat162 hp; hp.x = h0; hp.y = h1;
        hw = *(uint32_t*)&hp;
        lw = packbf(w0 - __bfloat162float(h0), w1 - __bfloat162float(h1));
    }
    g_Wfh[i] = hw;
    g_Wfl[i] = lw;
}

// ===================== conv2 via mma.sync bf16 split (HMMA), v7 =====================
// 2 CTAs/SM: two-pass B (hh+lh with Wfh, then hl with Wfl in the SAME buffer).
// 8 warps = 4 mg x 2 nh; per warp 4 m-tiles (dummy) x 4 n-tiles.
// smem: Tah 0 (29952), Tal 29952 (29952), Wbuf 59904 (43776). sD overlaps [0,50432).
// total 103680 <= 113664 (2 CTAs).
#define C2M_SMEM 103680

__global__ __launch_bounds__(256, 2) void k_conv2_mma(const float* __restrict__ cb)
{
    uint2* Tah  = (uint2*)dynsmem;                   // [288 rows][13]
    uint2* Tal  = (uint2*)(dynsmem + 29952);
    uint2* Wbuf = (uint2*)(dynsmem + 59904);         // [72 krows][76]
    float* sD   = (float*)dynsmem;                   // overlap after MMA passes
    __shared__ float ssc1[32], ssh1[32], sbias[64];

    int n = blockIdx.x, tid = threadIdx.x;
    int lane = tid & 31, w = tid >> 5;
    int g = lane >> 2, t = lane & 3;

    if (tid < 32) { ssc1[tid] = g_bn1[tid]; ssh1[tid] = g_bn1[32 + tid]; }
    if (tid < 64) sbias[tid] = cb[tid];

    {
        const uint2* gh = (const uint2*)g_Wfh;
        for (int i = tid; i < 5472; i += 256) Wbuf[i] = gh[i];
    }
    for (int i = tid; i < 3744; i += 256) {
        Tah[i] = make_uint2(0u, 0u);
        Tal[i] = make_uint2(0u, 0u);
    }
    __syncthreads();

    // input: BN1 select + relu, split hi/lo (stride 13 uint2, conflict-free)
    const float* mxp = g_h1max + n * 6272;
    const float* mnp = g_h1min + n * 6272;
    __nv_bfloat16* Th16 = (__nv_bfloat16*)Tah;
    __nv_bfloat16* Tl16 = (__nv_bfloat16*)Tal;
    for (int i = tid; i < 6272; i += 256) {
        int ci = i / 196, p = i % 196;
        float sc = ssc1[ci], sh = ssh1[ci];
        float base = (sc >= 0.f) ? mxp[i] : mnp[i];
        float v = fmaxf(fmaf(sc, base, sh), 0.f);
        __nv_bfloat16 hbf = __float2bfloat16_rn(v);
        float lf = v - __bfloat162float(hbf);
        int j = ci >> 1, hh = j >> 3, r = j & 7;
        int tt = r & 3, u = r >> 2;
        int row = (p / 14 + 1) * 16 + (p % 14 + 1);
        int word = row * 26 + (hh * 4 + tt) * 2 + u;
        Th16[word * 2 + (ci & 1)] = hbf;
        Tl16[word * 2 + (ci & 1)] = __float2bfloat16_rn(lf);
    }
    __syncthreads();

    // warp = (mg, nh): mg owns m-tiles mg+4*mi (dummy replays mg), nh owns n-tiles nh*4..+3
    int mg = w & 3, nh = w >> 2;
    int pixa[4], pixb[4], mas[4];
#pragma unroll
    for (int mi = 0; mi < 4; mi++) {
        int mt = mg + 4 * mi;
        bool real = mt < 13;
        int mt2 = real ? mt : mg;
        int ma = mt2 * 16 + g;
        int mb = ma + 8;
        mas[mi] = real ? ma : -1;
        pixa[mi] = ((ma / 14) * 16 + (ma % 14)) * 13;
        pixb[mi] = ((mb / 14) * 16 + (mb % 14)) * 13;
    }
    float acc[4][4][4];
#pragma unroll
    for (int mi = 0; mi < 4; mi++)
#pragma unroll
        for (int nt = 0; nt < 4; nt++)
#pragma unroll
            for (int c = 0; c < 4; c++) acc[mi][nt][c] = 0.f;

    int nb0 = nh * 32 + g;

    // ---- pass A: hh + lh (B = Wfh) ----
#pragma unroll 6
    for (int kt = 0; kt < 18; kt++) {
        int s = kt >> 1, hh = kt & 1;
        int off13 = ((s / 3) * 16 + (s % 3)) * 13;
        int wbase = (kt * 4 + t) * 76 + nb0;
        uint2 bh[4];
#pragma unroll
        for (int nt = 0; nt < 4; nt++) bh[nt] = Wbuf[wbase + nt * 8];
        int abase = off13 + hh * 4 + t;
#pragma unroll
        for (int mi = 0; mi < 4; mi++) {
            uint2 uah = Tah[pixa[mi] + abase];
            uint2 ubh = Tah[pixb[mi] + abase];
            uint2 ual = Tal[pixa[mi] + abase];
            uint2 ubl = Tal[pixb[mi] + abase];
#pragma unroll
            for (int nt = 0; nt < 4; nt++) {
                mma_bf16(acc[mi][nt], uah.x, ubh.x, uah.y, ubh.y, bh[nt].x, bh[nt].y);
                mma_bf16(acc[mi][nt], ual.x, ubl.x, ual.y, ubl.y, bh[nt].x, bh[nt].y);
            }
        }
    }
    __syncthreads();
    {
        const uint2* gl = (const uint2*)g_Wfl;
        for (int i = tid; i < 5472; i += 256) Wbuf[i] = gl[i];
    }
    __syncthreads();

    // ---- pass B: hl (B = Wfl, A hi only) ----
#pragma unroll 6
    for (int kt = 0; kt < 18; kt++) {
        int s = kt >> 1, hh = kt & 1;
        int off13 = ((s / 3) * 16 + (s % 3)) * 13;
        int wbase = (kt * 4 + t) * 76 + nb0;
        uint2 bl[4];
#pragma unroll
        for (int nt = 0; nt < 4; nt++) bl[nt] = Wbuf[wbase + nt * 8];
        int abase = off13 + hh * 4 + t;
#pragma unroll
        for (int mi = 0; mi < 4; mi++) {
            uint2 uah = Tah[pixa[mi] + abase];
            uint2 ubh = Tah[pixb[mi] + abase];
#pragma unroll
            for (int nt = 0; nt < 4; nt++)
                mma_bf16(acc[mi][nt], uah.x, ubh.x, uah.y, ubh.y, bl[nt].x, bl[nt].y);
        }
    }
    __syncthreads();                                 // T dead -> sD may overlap

#pragma unroll
    for (int mi = 0; mi < 4; mi++) {
        if (mas[mi] < 0) continue;
        int ma = mas[mi], mb = ma + 8;
#pragma unroll
        for (int nt = 0; nt < 4; nt++) {
            int oc = (nh * 4 + nt) * 8 + t * 2;
            if (ma < 196) {
                sD[oc * 197 + ma] = acc[mi][nt][0];
                sD[(oc + 1) * 197 + ma] = acc[mi][nt][1];
            }
            if (mb < 196) {
                sD[oc * 197 + mb] = acc[mi][nt][2];
                sD[(oc + 1) * 197 + mb] = acc[mi][nt][3];
            }
        }
    }
    __syncthreads();

    // ---- pooled max/min + BN2 stat partials (2 threads per oc) ----
    if (tid < 128) {
        int oc = tid >> 1, h = tid & 1;
        float b = sbias[oc];
        const float* row = sD + oc * 197;
        float s = 0.f, q = 0.f;
        for (int p2 = h * 98; p2 < h * 98 + 98; p2++) {
            float v = row[p2] + b;
            s += v; q = fmaf(v, v, q);
        }
        float s2 = s + __shfl_xor_sync(0xffffffffu, s, 1);
        float q2 = q + __shfl_xor_sync(0xffffffffu, q, 1);
        if (h == 0) {
            g_part2[n * 128 + oc] = s2;
            g_part2[n * 128 + 64 + oc] = q2;
        }
        int w0 = h * 25, w1 = (h == 0) ? 25 : 49;
        for (int ww = w0; ww < w1; ww++) {
            int wy = ww / 7, wx = ww - wy * 7;
            int pp = wy * 28 + 2 * wx;
            float u0 = row[pp] + b, u1 = row[pp + 1] + b;
            float u2 = row[pp + 14] + b, u3 = row[pp + 15] + b;
            int ob = (n * 64 + oc) * 49 + ww;
            g_o2max[ob] = fmaxf(fmaxf(u0, u1), fmaxf(u2, u3));
            g_o2min[ob] = fminf(fminf(u0, u1), fminf(u2, u3));
        }
    }
}

// ===== fc1 (BN2 select on pooled arrays; coalesced) =====
__global__ __launch_bounds__(256) void k_fc1(const float* __restrict__ fw)
{
    __shared__ float As[32][65], Bs[32][130];
    int m0 = blockIdx.x * 64, z = blockIdx.y;
    int kt0 = ((98 * z) / 8) * 32, kt1 = ((98 * (z + 1)) / 8) * 32;
    int tid = threadIdx.x, tx = tid & 31, ty = tid >> 5;
    float acc[8][4];
#pragma unroll
    for (int u = 0; u < 8; u++)
#pragma unroll
        for (int v = 0; v < 4; v++) acc[u][v] = 0.f;
    for (int k0 = kt0; k0 < kt1; k0 += 32) {
        for (int i = tid; i < 2048; i += 256) {
            int r = i >> 5, c = i & 31;
            int kk = k0 + c;
            int oc = kk / 49, p = kk - oc * 49;
            float sc = __ldg(&g_bn2[oc]), sh = __ldg(&g_bn2[64 + oc]);
            int off = ((m0 + r) * 64 + oc) * 49 + p;
            float base = (sc >= 0.f) ? g_o2max[off] : g_o2min[off];
            As[c][r] = fmaxf(fmaf(sc, base, sh), 0.f);
        }
        for (int i = tid; i < 4096; i += 256) {
            int r = i >> 5, c = i & 31;
            Bs[c][r] = fw[r * 3136 + k0 + c];
        }
        __syncthreads();
#pragma unroll
        for (int k = 0; k < 32; k++) {
            float a[8], b[4];
#pragma unroll
            for (int u = 0; u < 8; u++) a[u] = As[k][ty * 8 + u];
#pragma unroll
            for (int v = 0; v < 4; v++) b[v] = Bs[k][tx * 4 + v];
#pragma unroll
            for (int u = 0; u < 8; u++)
#pragma unroll
                for (int v = 0; v < 4; v++) acc[u][v] = fmaf(a[u], b[v], acc[u][v]);
        }
        __syncthreads();
    }
    float* pp = g_fcpart + z * (NB * 128);
#pragma unroll
    for (int u = 0; u < 8; u++)
#pragma unroll
        for (int v = 0; v < 4; v++)
            pp[(m0 + ty * 8 + u) * 128 + tx * 4 + v] = acc[u][v];
}

__global__ __launch_bounds__(256) void k_fc1combine(const float* __restrict__ fb)
{
    int idx = blockIdx.x * 256 + threadIdx.x;
    if (idx >= NB * 128) return;
    float v = fb[idx & 127];
#pragma unroll
    for (int z = 0; z < 8; z++) v += g_fcpart[z * (NB * 128) + idx];
    g_feat[idx] = fmaxf(v, 0.f);
}

// ===== SYRK chunk partials =====
__global__ __launch_bounds__(256) void k_syrk()
{
    __shared__ float As[64][33], Bs[64][33];
    int ti = blockIdx.x, tj = blockIdx.y, ch = blockIdx.z;
    int tid = threadIdx.x, tx = tid & 15, ty = tid >> 4, n0 = ch * 64;
    for (int i = tid; i < 2048; i += 256) {
        int r = i >> 5, c = i & 31;
        int gi = ti * 32 + c, gj = tj * 32 + c;
        As[r][c] = (gi < 128) ? g_feat[(n0 + r) * 128 + gi] : (gi == 128 ? 1.f : 0.f);
        Bs[r][c] = (gj < 128) ? g_feat[(n0 + r) * 128 + gj] : (gj == 128 ? 1.f : 0.f);
    }
    __syncthreads();
    float a00 = 0.f, a01 = 0.f, a10 = 0.f, a11 = 0.f;
#pragma unroll 8
    for (int k = 0; k < 64; k++) {
        float x0 = As[k][2 * ty], x1 = As[k][2 * ty + 1];
        float y0 = Bs[k][2 * tx], y1 = Bs[k][2 * tx + 1];
        a00 = fmaf(x0, y0, a00); a01 = fmaf(x0, y1, a01);
        a10 = fmaf(x1, y0, a10); a11 = fmaf(x1, y1, a11);
    }
    float* pa = g_partA + ch * 16641;
    int gi0 = ti * 32 + 2 * ty, gj0 = tj * 32 + 2 * tx;
    if (gi0 < 129 && gj0 < 129) pa[gi0 * 129 + gj0] = a00;
    if (gi0 < 129 && gj0 + 1 < 129) pa[gi0 * 129 + gj0 + 1] = a01;
    if (gi0 + 1 < 129 && gj0 < 129) pa[(gi0 + 1) * 129 + gj0] = a10;
    if (gi0 + 1 < 129 && gj0 + 1 < 129) pa[(gi0 + 1) * 129 + gj0 + 1] = a11;
}

__global__ __launch_bounds__(256) void k_reduceA()
{
    int o = blockIdx.x * 256 + threadIdx.x;
    if (o >= 16641) return;
    double s = ((o / 129) == (o % 129)) ? 1.0 : 0.0;
    for (int ch = 0; ch < 64; ch++) s += (double)g_partA[ch * 16641 + o];
    g_A[o] = s;
}

// ===== Phi^T Y chunk partials =====
__global__ __launch_bounds__(256) void k_phity(const float* __restrict__ y)
{
    __shared__ float sf[64 * 129], sy[640];
    int ch = blockIdx.x, n0 = ch * 64, tid = threadIdx.x;
    for (int i = tid; i < 8192; i += 256)
        sf[(i >> 7) * 129 + (i & 127)] = g_feat[(n0 + (i >> 7)) * 128 + (i & 127)];
    for (int i = tid; i < 64; i += 256) sf[i * 129 + 128] = 1.f;
    for (int i = tid; i < 640; i += 256) sy[i] = y[n0 * 10 + i];
    __syncthreads();
    for (int o = tid; o < 1290; o += 256) {
        int i = o / 10, c = o % 10;
        float s = 0.f;
        for (int r = 0; r < 64; r++) s = fmaf(sf[r * 129 + i], sy[r * 10 + c], s);
        g_partB[ch * 1290 + o] = s;
    }
}

__global__ __launch_bounds__(256) void k_Bfinal(const float* __restrict__ Wrls)
{
    int o = blockIdx.x * 256 + threadIdx.x;
    if (o >= 1290) return;
    double s = (double)Wrls[o];
    for (int ch = 0; ch < 64; ch++) s += (double)g_partB[ch * 1290 + o];
    g_Bm[o] = s;
}

// ===== fp64 Cholesky + 10-RHS solve (lower-triangle updates only) =====
__global__ __launch_bounds__(256) void k_chol(const float* __restrict__ Wrls,
                                              const int* __restrict__ sep)
{
    double* A = (double*)dynsmem;
    double* Bv = A + 129 * 130;
    int tid = threadIdx.x;
    if (sep[0] == 0) {
        for (int i = tid; i < 1290; i += 256) g_W[i] = Wrls[i];
        return;
    }
    for (int i = tid; i < 16641; i += 256) A[(i / 129) * 130 + (i % 129)] = g_A[i];
    for (int i = tid; i < 1290; i += 256) Bv[i] = g_Bm[i];
    __syncthreads();
    __shared__ double sinv;
    for (int k = 0; k < 129; k++) {
        if (tid == 0) {
            double d = sqrt(A[k * 130 + k]);
            A[k * 130 + k] = d;
            sinv = 1.0 / d;
        }
        __syncthreads();
        double iv = sinv;
        for (int i = k + 1 + tid; i < 129; i += 256) A[i * 130 + k] *= iv;
        __syncthreads();
        int m = 128 - k;
        for (int t = tid; t < m * m; t += 256) {
            int i = k + 1 + t / m, j = k + 1 + t % m;
            if (j <= i)
                A[i * 130 + j] -= A[i * 130 + k] * A[j * 130 + k];
        }
        __syncthreads();
    }
    for (int k = 0; k < 129; k++) {
        if (tid < 10) Bv[k * 10 + tid] /= A[k * 130 + k];
        __syncthreads();
        for (int t = tid; t < (128 - k) * 10; t += 256) {
            int i = k + 1 + t / 10, c = t % 10;
            Bv[i * 10 + c] -= A[i * 130 + k] * Bv[k * 10 + c];
        }
        __syncthreads();
    }
    for (int k = 128; k >= 0; k--) {
        if (tid < 10) Bv[k * 10 + tid] /= A[k * 130 + k];
        __syncthreads();
        for (int t = tid; t < k * 10; t += 256) {
            int i = t / 10, c = t % 10;
            Bv[i * 10 + c] -= A[k * 130 + i] * Bv[k * 10 + c];
        }
        __syncthreads();
    }
    for (int i = tid; i < 1290; i += 256) g_W[i] = (float)Bv[i];
}

// ===== head =====
__global__ __launch_bounds__(256) void k_head(float* __restrict__ out)
{
    __shared__ float sW[1290];
    int tid = threadIdx.x;
    for (int i = tid; i < 1290; i += 256) sW[i] = g_W[i];
    __syncthreads();
    int idx = blockIdx.x * 256 + tid;
    if (idx >= NB * 10) return;
    int n = idx / 10, c = idx % 10;
    float acc = sW[1280 + c];
    const float* f = g_feat + n * 128;
#pragma unroll 8
    for (int i = 0; i < 128; i++) acc = fmaf(f[i], sW[i * 10 + c], acc);
    out[idx] = acc;
}

extern "C" void kernel_launch(void* const* d_in, const int* in_sizes, int n_in,
                              void* d_out, int out_size)
{
    const float* x       = (const float*)d_in[0];
    const float* y       = (const float*)d_in[1];
    const float* conv1_w = (const float*)d_in[2];
    const float* conv1_b = (const float*)d_in[3];
    const float* bn1_g   = (const float*)d_in[4];
    const float* bn1_b   = (const float*)d_in[5];
    const float* conv2_w = (const float*)d_in[6];
    const float* conv2_b = (const float*)d_in[7];
    const float* bn2_g   = (const float*)d_in[8];
    const float* bn2_b   = (const float*)d_in[9];
    const float* fc1_w   = (const float*)d_in[10];
    const float* fc1_b   = (const float*)d_in[11];
    const float* W_rls   = (const float*)d_in[12];
    const int*   sep     = (const int*)d_in[14];
    float* out = (float*)d_out;

    cudaFuncSetAttribute(k_conv2_mma, cudaFuncAttributeMaxDynamicSharedMemorySize, C2M_SMEM);
    cudaFuncSetAttribute(k_chol, cudaFuncAttributeMaxDynamicSharedMemorySize, 144480);

    float* p1; cudaGetSymbolAddress((void**)&p1, g_part1);
    float* p2; cudaGetSymbolAddress((void**)&p2, g_part2);
    float* b1; cudaGetSymbolAddress((void**)&b1, g_bn1);
    float* b2; cudaGetSymbolAddress((void**)&b2, g_bn2);

    k_prepw<<<86, 256>>>(conv2_w);
    k_conv1_mmx<<<NB, 224>>>(x, conv1_w, conv1_b);
    k_bnfinal<<<32, 256>>>(bn1_g, bn1_b, p1, b1, 32, 1.f / (float)(NB * 784));
    k_conv2_mma<<<NB, 256, C2M_SMEM>>>(conv2_b);
    k_bnfinal<<<64, 256>>>(bn2_g, bn2_b, p2, b2, 64, 1.f / (float)(NB * 196));
    k_fc1<<<dim3(64, 8), 256>>>(fc1_w);
    k_fc1combine<<<(NB * 128) / 256, 256>>>(fc1_b);
    k_syrk<<<dim3(5, 5, 64), 256>>>();
    k_reduceA<<<66, 256>>>();
    k_phity<<<64, 256>>>(y);
    k_Bfinal<<<6, 256>>>(W_rls);
    k_chol<<<1, 256, 144480>>>(W_rls, sep);
    k_head<<<(NB * 10 + 255) / 256, 256>>>(out);
}

// round 16
// speedup vs baseline: 1.1314x; 1.0088x over previous
#include <cuda_runtime.h>
#include <cuda_bf16.h>
#include <math.h>
#include <cstdint>

#define NB 4096

// ----- scratch (device globals; no allocations) -----
__device__ float  g_h1max[NB * 32 * 196];
__device__ float  g_h1min[NB * 32 * 196];
__device__ float  g_o2max[NB * 64 * 49];
__device__ float  g_o2min[NB * 64 * 49];
__device__ float  g_feat[NB * 128];
__device__ float  g_part1[NB * 64];
__device__ float  g_part2[NB * 128];
__device__ float  g_bn1[64];
__device__ float  g_bn2[128];
__device__ float  g_fcpart[8 * NB * 128];
__device__ float  g_partA[64 * 129 * 129];
__device__ float  g_partB[64 * 1290];
__device__ double g_A[129 * 129];
__device__ double g_Bm[1290];
__device__ float  g_W[1290];
__device__ uint32_t g_Wfh[21888];      // 72 krows x 76 (padded) x uint2
__device__ uint32_t g_Wfl[21888];

extern __shared__ char dynsmem[];

__device__ __forceinline__ void mma_bf16(float* c, uint32_t a0, uint32_t a1,
                                         uint32_t a2, uint32_t a3,
                                         uint32_t b0, uint32_t b1)
{
    asm volatile(
        "mma.sync.aligned.m16n8k16.row.col.f32.bf16.bf16.f32 "
        "{%0,%1,%2,%3}, {%4,%5,%6,%7}, {%8,%9}, {%0,%1,%2,%3};"
        : "+f"(c[0]), "+f"(c[1]), "+f"(c[2]), "+f"(c[3])
        : "r"(a0), "r"(a1), "r"(a2), "r"(a3), "r"(b0), "r"(b1));
}

__device__ __forceinline__ uint32_t packbf(float v0, float v1)
{
    __nv_bfloat162 p = __floats2bfloat162_rn(v0, v1);
    return *(uint32_t*)&p;
}

// ===== conv1 single pass: raw-conv window max/min + BN stats =====
__global__ __launch_bounds__(224) void k_conv1_mmx(
    const float* __restrict__ x, const float* __restrict__ w, const float* __restrict__ bias)
{
    __shared__ float simg[900], sw[288], sb[32], wred[7][64];
    int n = blockIdx.x, tid = threadIdx.x;
    for (int i = tid; i < 900; i += 224) simg[i] = 0.f;
    for (int i = tid; i < 288; i += 224) sw[i] = w[i];
    if (tid < 32) sb[tid] = bias[tid];
    __syncthreads();
    const float* xi = x + n * 784;
    for (int i = tid; i < 784; i += 224)
        simg[(i / 28 + 1) * 30 + (i % 28) + 1] = xi[i];
    __syncthreads();

    float ls[32], lq[32];
#pragma unroll
    for (int c = 0; c < 32; c++) { ls[c] = 0.f; lq[c] = 0.f; }

    if (tid < 196) {
        int py = tid / 14, px = tid % 14;
        float patch[16];
#pragma unroll
        for (int dy = 0; dy < 4; dy++)
#pragma unroll
            for (int dx = 0; dx < 4; dx++)
                patch[dy * 4 + dx] = simg[(2 * py + dy) * 30 + 2 * px + dx];
#pragma unroll
        for (int oc = 0; oc < 32; oc++) {
            float v[4];
#pragma unroll
            for (int dy = 0; dy < 2; dy++)
#pragma unroll
                for (int dx = 0; dx < 2; dx++) {
                    float a = sb[oc];
#pragma unroll
                    for (int ky = 0; ky < 3; ky++)
#pragma unroll
                        for (int kx = 0; kx < 3; kx++)
                            a = fmaf(sw[oc * 9 + ky * 3 + kx],
                                     patch[(dy + ky) * 4 + dx + kx], a);
                    v[dy * 2 + dx] = a;
                }
            float mx = fmaxf(fmaxf(v[0], v[1]), fmaxf(v[2], v[3]));
            float mn = fminf(fminf(v[0], v[1]), fminf(v[2], v[3]));
            g_h1max[(n * 32 + oc) * 196 + tid] = mx;
            g_h1min[(n * 32 + oc) * 196 + tid] = mn;
            ls[oc] += (v[0] + v[1]) + (v[2] + v[3]);
            lq[oc] = fmaf(v[0], v[0], fmaf(v[1], v[1], fmaf(v[2], v[2], fmaf(v[3], v[3], lq[oc]))));
        }
    }
    int lane = tid & 31, wid = tid >> 5;
#pragma unroll
    for (int oc = 0; oc < 32; oc++) {
        float s = ls[oc], q = lq[oc];
#pragma unroll
        for (int o = 16; o > 0; o >>= 1) {
            s += __shfl_down_sync(0xffffffffu, s, o);
            q += __shfl_down_sync(0xffffffffu, q, o);
        }
        if (lane == 0) { wred[wid][oc] = s; wred[wid][32 + oc] = q; }
    }
    __syncthreads();
    if (tid < 64) {
        float s = 0.f;
#pragma unroll
        for (int w7 = 0; w7 < 7; w7++) s += wred[w7][tid];
        g_part1[n * 64 + tid] = s;
    }
}

// ===== BN finalize =====
__global__ __launch_bounds__(256) void k_bnfinal(
    const float* __restrict__ gamma, const float* __restrict__ beta,
    const float* __restrict__ part, float* __restrict__ bn, int nc, float invN)
{
    int c = blockIdx.x, tid = threadIdx.x;
    float s = 0.f, q = 0.f;
    for (int r = tid; r < NB; r += 256) {
        s += part[r * 2 * nc + c];
        q += part[r * 2 * nc + nc + c];
    }
    __shared__ float ss[256], sq[256];
    ss[tid] = s; sq[tid] = q; __syncthreads();
    for (int o = 128; o > 0; o >>= 1) {
        if (tid < o) { ss[tid] += ss[tid + o]; sq[tid] += sq[tid + o]; }
        __syncthreads();
    }
    if (tid == 0) {
        float mean = ss[0] * invN;
        float var = sq[0] * invN - mean * mean;
        float scale = gamma[c] * rsqrtf(var + 1e-5f);
        bn[c] = scale;
        bn[nc + c] = beta[c] - mean * scale;
    }
}

// ===== weight fragment prep (once): pair-packed hi/lo, PADDED stride 76 =====
__global__ __launch_bounds__(256) void k_prepw(const float* __restrict__ cw)
{
    int i = blockIdx.x * 256 + threadIdx.x;
    if (i >= 21888) return;
    int pair = i >> 1, u = i & 1;
    int krow = pair / 76, nb = pair % 76;
    int kt = krow >> 2, t = krow & 3;
    uint32_t hw = 0, lw = 0;
    if (nb < 64) {
        int srow = kt * 8 + t + 4 * u;
        int s9 = srow >> 4, j = srow & 15;
        float w0 = cw[nb * 288 + 2 * j * 9 + s9];
        float w1 = cw[nb * 288 + (2 * j + 1) * 9 + s9];
        __nv_bfloat16 h0 = __float2bfloat16_rn(w0);
        __nv_bfloat16 h1 = __float2bfloat16_rn(w1);
        __nv_bfloat162 hp; hp.x = h0; hp.y = h1;
        hw = *(uint32_t*)&hp;
        lw = packbf(w0 - __bfloat162float(h0), w1 - __bfloat162float(h1));
    }
    g_Wfh[i] = hw;
    g_Wfl[i] = lw;
}

// ===================== conv2 via mma.sync bf16 split (HMMA), v7 =====================
// 2 CTAs/SM: two-pass B (hh+lh with Wfh, then hl with Wfl in the SAME buffer).
#define C2M_SMEM 103680

__global__ __launch_bounds__(256, 2) void k_conv2_mma(const float* __restrict__ cb)
{
    uint2* Tah  = (uint2*)dynsmem;                   // [288 rows][13]
    uint2* Tal  = (uint2*)(dynsmem + 29952);
    uint2* Wbuf = (uint2*)(dynsmem + 59904);         // [72 krows][76]
    float* sD   = (float*)dynsmem;                   // overlap after MMA passes
    __shared__ float ssc1[32], ssh1[32], sbias[64];

    int n = blockIdx.x, tid = threadIdx.x;
    int lane = tid & 31, w = tid >> 5;
    int g = lane >> 2, t = lane & 3;

    if (tid < 32) { ssc1[tid] = g_bn1[tid]; ssh1[tid] = g_bn1[32 + tid]; }
    if (tid < 64) sbias[tid] = cb[tid];

    {
        const uint2* gh = (const uint2*)g_Wfh;
        for (int i = tid; i < 5472; i += 256) Wbuf[i] = gh[i];
    }
    for (int i = tid; i < 3744; i += 256) {
        Tah[i] = make_uint2(0u, 0u);
        Tal[i] = make_uint2(0u, 0u);
    }
    __syncthreads();

    const float* mxp = g_h1max + n * 6272;
    const float* mnp = g_h1min + n * 6272;
    __nv_bfloat16* Th16 = (__nv_bfloat16*)Tah;
    __nv_bfloat16* Tl16 = (__nv_bfloat16*)Tal;
    for (int i = tid; i < 6272; i += 256) {
        int ci = i / 196, p = i % 196;
        float sc = ssc1[ci], sh = ssh1[ci];
        float base = (sc >= 0.f) ? mxp[i] : mnp[i];
        float v = fmaxf(fmaf(sc, base, sh), 0.f);
        __nv_bfloat16 hbf = __float2bfloat16_rn(v);
        float lf = v - __bfloat162float(hbf);
        int j = ci >> 1, hh = j >> 3, r = j & 7;
        int tt = r & 3, u = r >> 2;
        int row = (p / 14 + 1) * 16 + (p % 14 + 1);
        int word = row * 26 + (hh * 4 + tt) * 2 + u;
        Th16[word * 2 + (ci & 1)] = hbf;
        Tl16[word * 2 + (ci & 1)] = __float2bfloat16_rn(lf);
    }
    __syncthreads();

    int mg = w & 3, nh = w >> 2;
    int pixa[4], pixb[4], mas[4];
#pragma unroll
    for (int mi = 0; mi < 4; mi++) {
        int mt = mg + 4 * mi;
        bool real = mt < 13;
        int mt2 = real ? mt : mg;
        int ma = mt2 * 16 + g;
        int mb = ma + 8;
        mas[mi] = real ? ma : -1;
        pixa[mi] = ((ma / 14) * 16 + (ma % 14)) * 13;
        pixb[mi] = ((mb / 14) * 16 + (mb % 14)) * 13;
    }
    float acc[4][4][4];
#pragma unroll
    for (int mi = 0; mi < 4; mi++)
#pragma unroll
        for (int nt = 0; nt < 4; nt++)
#pragma unroll
            for (int c = 0; c < 4; c++) acc[mi][nt][c] = 0.f;

    int nb0 = nh * 32 + g;

    // ---- pass A: hh + lh (B = Wfh) ----
#pragma unroll 6
    for (int kt = 0; kt < 18; kt++) {
        int s = kt >> 1, hh = kt & 1;
        int off13 = ((s / 3) * 16 + (s % 3)) * 13;
        int wbase = (kt * 4 + t) * 76 + nb0;
        uint2 bh[4];
#pragma unroll
        for (int nt = 0; nt < 4; nt++) bh[nt] = Wbuf[wbase + nt * 8];
        int abase = off13 + hh * 4 + t;
#pragma unroll
        for (int mi = 0; mi < 4; mi++) {
            uint2 uah = Tah[pixa[mi] + abase];
            uint2 ubh = Tah[pixb[mi] + abase];
            uint2 ual = Tal[pixa[mi] + abase];
            uint2 ubl = Tal[pixb[mi] + abase];
#pragma unroll
            for (int nt = 0; nt < 4; nt++) {
                mma_bf16(acc[mi][nt], uah.x, ubh.x, uah.y, ubh.y, bh[nt].x, bh[nt].y);
                mma_bf16(acc[mi][nt], ual.x, ubl.x, ual.y, ubl.y, bh[nt].x, bh[nt].y);
            }
        }
    }
    __syncthreads();
    {
        const uint2* gl = (const uint2*)g_Wfl;
        for (int i = tid; i < 5472; i += 256) Wbuf[i] = gl[i];
    }
    __syncthreads();

    // ---- pass B: hl (B = Wfl, A hi only) ----
#pragma unroll 6
    for (int kt = 0; kt < 18; kt++) {
        int s = kt >> 1, hh = kt & 1;
        int off13 = ((s / 3) * 16 + (s % 3)) * 13;
        int wbase = (kt * 4 + t) * 76 + nb0;
        uint2 bl[4];
#pragma unroll
        for (int nt = 0; nt < 4; nt++) bl[nt] = Wbuf[wbase + nt * 8];
        int abase = off13 + hh * 4 + t;
#pragma unroll
        for (int mi = 0; mi < 4; mi++) {
            uint2 uah = Tah[pixa[mi] + abase];
            uint2 ubh = Tah[pixb[mi] + abase];
#pragma unroll
            for (int nt = 0; nt < 4; nt++)
                mma_bf16(acc[mi][nt], uah.x, ubh.x, uah.y, ubh.y, bl[nt].x, bl[nt].y);
        }
    }
    __syncthreads();

#pragma unroll
    for (int mi = 0; mi < 4; mi++) {
        if (mas[mi] < 0) continue;
        int ma = mas[mi], mb = ma + 8;
#pragma unroll
        for (int nt = 0; nt < 4; nt++) {
            int oc = (nh * 4 + nt) * 8 + t * 2;
            if (ma < 196) {
                sD[oc * 197 + ma] = acc[mi][nt][0];
                sD[(oc + 1) * 197 + ma] = acc[mi][nt][1];
            }
            if (mb < 196) {
                sD[oc * 197 + mb] = acc[mi][nt][2];
                sD[(oc + 1) * 197 + mb] = acc[mi][nt][3];
            }
        }
    }
    __syncthreads();

    if (tid < 128) {
        int oc = tid >> 1, h = tid & 1;
        float b = sbias[oc];
        const float* row = sD + oc * 197;
        float s = 0.f, q = 0.f;
        for (int p2 = h * 98; p2 < h * 98 + 98; p2++) {
            float v = row[p2] + b;
            s += v; q = fmaf(v, v, q);
        }
        float s2 = s + __shfl_xor_sync(0xffffffffu, s, 1);
        float q2 = q + __shfl_xor_sync(0xffffffffu, q, 1);
        if (h == 0) {
            g_part2[n * 128 + oc] = s2;
            g_part2[n * 128 + 64 + oc] = q2;
        }
        int w0 = h * 25, w1 = (h == 0) ? 25 : 49;
        for (int ww = w0; ww < w1; ww++) {
            int wy = ww / 7, wx = ww - wy * 7;
            int pp = wy * 28 + 2 * wx;
            float u0 = row[pp] + b, u1 = row[pp + 1] + b;
            float u2 = row[pp + 14] + b, u3 = row[pp + 15] + b;
            int ob = (n * 64 + oc) * 49 + ww;
            g_o2max[ob] = fmaxf(fmaxf(u0, u1), fmaxf(u2, u3));
            g_o2min[ob] = fminf(fminf(u0, u1), fminf(u2, u3));
        }
    }
}

// ===== fc1 (BN2 select on pooled arrays; vectorized B reads) =====
__global__ __launch_bounds__(256) void k_fc1(const float* __restrict__ fw)
{
    __shared__ float As[32][65];
    __shared__ __align__(16) float Bs[32 * 132];
    int m0 = blockIdx.x * 64, z = blockIdx.y;
    int kt0 = ((98 * z) / 8) * 32, kt1 = ((98 * (z + 1)) / 8) * 32;
    int tid = threadIdx.x, tx = tid & 31, ty = tid >> 5;
    float acc[8][4];
#pragma unroll
    for (int u = 0; u < 8; u++)
#pragma unroll
        for (int v = 0; v < 4; v++) acc[u][v] = 0.f;
    for (int k0 = kt0; k0 < kt1; k0 += 32) {
        for (int i = tid; i < 2048; i += 256) {
            int r = i >> 5, c = i & 31;
            int kk = k0 + c;
            int oc = kk / 49, p = kk - oc * 49;
            float sc = __ldg(&g_bn2[oc]), sh = __ldg(&g_bn2[64 + oc]);
            int off = ((m0 + r) * 64 + oc) * 49 + p;
            float base = (sc >= 0.f) ? g_o2max[off] : g_o2min[off];
            As[c][r] = fmaxf(fmaf(sc, base, sh), 0.f);
        }
        for (int i = tid; i < 4096; i += 256) {
            int r = i >> 5, c = i & 31;
            Bs[c * 132 + r] = fw[r * 3136 + k0 + c];
        }
        __syncthreads();
#pragma unroll
        for (int k = 0; k < 32; k++) {
            float a[8];
#pragma unroll
            for (int u = 0; u < 8; u++) a[u] = As[k][ty * 8 + u];
            float4 b4 = ((const float4*)&Bs[k * 132])[tx];
            float b[4] = {b4.x, b4.y, b4.z, b4.w};
#pragma unroll
            for (int u = 0; u < 8; u++)
#pragma unroll
                for (int v = 0; v < 4; v++) acc[u][v] = fmaf(a[u], b[v], acc[u][v]);
        }
        __syncthreads();
    }
    float* pp = g_fcpart + z * (NB * 128);
#pragma unroll
    for (int u = 0; u < 8; u++)
#pragma unroll
        for (int v = 0; v < 4; v++)
            pp[(m0 + ty * 8 + u) * 128 + tx * 4 + v] = acc[u][v];
}

__global__ __launch_bounds__(256) void k_fc1combine(const float* __restrict__ fb)
{
    int idx = blockIdx.x * 256 + threadIdx.x;
    if (idx >= NB * 128) return;
    float v = fb[idx & 127];
#pragma unroll
    for (int z = 0; z < 8; z++) v += g_fcpart[z * (NB * 128) + idx];
    g_feat[idx] = fmaxf(v, 0.f);
}

// ===== SYRK chunk partials =====
__global__ __launch_bounds__(256) void k_syrk()
{
    __shared__ float As[64][33], Bs[64][33];
    int ti = blockIdx.x, tj = blockIdx.y, ch = blockIdx.z;
    int tid = threadIdx.x, tx = tid & 15, ty = tid >> 4, n0 = ch * 64;
    for (int i = tid; i < 2048; i += 256) {
        int r = i >> 5, c = i & 31;
        int gi = ti * 32 + c, gj = tj * 32 + c;
        As[r][c] = (gi < 128) ? g_feat[(n0 + r) * 128 + gi] : (gi == 128 ? 1.f : 0.f);
        Bs[r][c] = (gj < 128) ? g_feat[(n0 + r) * 128 + gj] : (gj == 128 ? 1.f : 0.f);
    }
    __syncthreads();
    float a00 = 0.f, a01 = 0.f, a10 = 0.f, a11 = 0.f;
#pragma unroll 8
    for (int k = 0; k < 64; k++) {
        float x0 = As[k][2 * ty], x1 = As[k][2 * ty + 1];
        float y0 = Bs[k][2 * tx], y1 = Bs[k][2 * tx + 1];
        a00 = fmaf(x0, y0, a00); a01 = fmaf(x0, y1, a01);
        a10 = fmaf(x1, y0, a10); a11 = fmaf(x1, y1, a11);
    }
    float* pa = g_partA + ch * 16641;
    int gi0 = ti * 32 + 2 * ty, gj0 = tj * 32 + 2 * tx;
    if (gi0 < 129 && gj0 < 129) pa[gi0 * 129 + gj0] = a00;
    if (gi0 < 129 && gj0 + 1 < 129) pa[gi0 * 129 + gj0 + 1] = a01;
    if (gi0 + 1 < 129 && gj0 < 129) pa[(gi0 + 1) * 129 + gj0] = a10;
    if (gi0 + 1 < 129 && gj0 + 1 < 129) pa[(gi0 + 1) * 129 + gj0 + 1] = a11;
}

__global__ __launch_bounds__(256) void k_reduceA()
{
    int o = blockIdx.x * 256 + threadIdx.x;
    if (o >= 16641) return;
    double s = ((o / 129) == (o % 129)) ? 1.0 : 0.0;
    for (int ch = 0; ch < 64; ch++) s += (double)g_partA[ch * 16641 + o];
    g_A[o] = s;
}

// ===== Phi^T Y chunk partials =====
__global__ __launch_bounds__(256) void k_phity(const float* __restrict__ y)
{
    __shared__ float sf[64 * 129], sy[640];
    int ch = blockIdx.x, n0 = ch * 64, tid = threadIdx.x;
    for (int i = tid; i < 8192; i += 256)
        sf[(i >> 7) * 129 + (i & 127)] = g_feat[(n0 + (i >> 7)) * 128 + (i & 127)];
    for (int i = tid; i < 64; i += 256) sf[i * 129 + 128] = 1.f;
    for (int i = tid; i < 640; i += 256) sy[i] = y[n0 * 10 + i];
    __syncthreads();
    for (int o = tid; o < 1290; o += 256) {
        int i = o / 10, c = o % 10;
        float s = 0.f;
        for (int r = 0; r < 64; r++) s = fmaf(sf[r * 129 + i], sy[r * 10 + c], s);
        g_partB[ch * 1290 + o] = s;
    }
}

__global__ __launch_bounds__(256) void k_Bfinal(const float* __restrict__ Wrls)
{
    int o = blockIdx.x * 256 + threadIdx.x;
    if (o >= 1290) return;
    double s = (double)Wrls[o];
    for (int ch = 0; ch < 64; ch++) s += (double)g_partB[ch * 1290 + o];
    g_Bm[o] = s;
}

// ===== fp64 Cholesky + 10-RHS solve (lower-triangle updates only) =====
__global__ __launch_bounds__(256) void k_chol(const float* __restrict__ Wrls,
                                              const int* __restrict__ sep)
{
    double* A = (double*)dynsmem;
    double* Bv = A + 129 * 130;
    int tid = threadIdx.x;
    if (sep[0] == 0) {
        for (int i = tid; i < 1290; i += 256) g_W[i] = Wrls[i];
        return;
    }
    for (int i = tid; i < 16641; i += 256) A[(i / 129) * 130 + (i % 129)] = g_A[i];
    for (int i = tid; i < 1290; i += 256) Bv[i] = g_Bm[i];
    __syncthreads();
    __shared__ double sinv;
    for (int k = 0; k < 129; k++) {
        if (tid == 0) {
            double d = sqrt(A[k * 130 + k]);
            A[k * 130 + k] = d;
            sinv = 1.0 / d;
        }
        __syncthreads();
        double iv = sinv;
        for (int i = k + 1 + tid; i < 129; i += 256) A[i * 130 + k] *= iv;
        __syncthreads();
        int m = 128 - k;
        for (int t = tid; t < m * m; t += 256) {
            int i = k + 1 + t / m, j = k + 1 + t % m;
            if (j <= i)
                A[i * 130 + j] -= A[i * 130 + k] * A[j * 130 + k];
        }
        __syncthreads();
    }
    for (int k = 0; k < 129; k++) {
        if (tid < 10) Bv[k * 10 + tid] /= A[k * 130 + k];
        __syncthreads();
        for (int t = tid; t < (128 - k) * 10; t += 256) {
            int i = k + 1 + t / 10, c = t % 10;
            Bv[i * 10 + c] -= A[i * 130 + k] * Bv[k * 10 + c];
        }
        __syncthreads();
    }
    for (int k = 128; k >= 0; k--) {
        if (tid < 10) Bv[k * 10 + tid] /= A[k * 130 + k];
        __syncthreads();
        for (int t = tid; t < k * 10; t += 256) {
            int i = t / 10, c = t % 10;
            Bv[i * 10 + c] -= A[k * 130 + i] * Bv[k * 10 + c];
        }
        __syncthreads();
    }
    for (int i = tid; i < 1290; i += 256) g_W[i] = (float)Bv[i];
}

// ===== head =====
__global__ __launch_bounds__(256) void k_head(float* __restrict__ out)
{
    __shared__ float sW[1290];
    int tid = threadIdx.x;
    for (int i = tid; i < 1290; i += 256) sW[i] = g_W[i];
    __syncthreads();
    int idx = blockIdx.x * 256 + tid;
    if (idx >= NB * 10) return;
    int n = idx / 10, c = idx % 10;
    float acc = sW[1280 + c];
    const float* f = g_feat + n * 128;
#pragma unroll 8
    for (int i = 0; i < 128; i++) acc = fmaf(f[i], sW[i * 10 + c], acc);
    out[idx] = acc;
}

extern "C" void kernel_launch(void* const* d_in, const int* in_sizes, int n_in,
                              void* d_out, int out_size)
{
    const float* x       = (const float*)d_in[0];
    const float* y       = (const float*)d_in[1];
    const float* conv1_w = (const float*)d_in[2];
    const float* conv1_b = (const float*)d_in[3];
    const float* bn1_g   = (const float*)d_in[4];
    const float* bn1_b   = (const float*)d_in[5];
    const float* conv2_w = (const float*)d_in[6];
    const float* conv2_b = (const float*)d_in[7];
    const float* bn2_g   = (const float*)d_in[8];
    const float* bn2_b   = (const float*)d_in[9];
    const float* fc1_w   = (const float*)d_in[10];
    const float* fc1_b   = (const float*)d_in[11];
    const float* W_rls   = (const float*)d_in[12];
    const int*   sep     = (const int*)d_in[14];
    float* out = (float*)d_out;

    cudaFuncSetAttribute(k_conv2_mma, cudaFuncAttributeMaxDynamicSharedMemorySize, C2M_SMEM);
    cudaFuncSetAttribute(k_chol, cudaFuncAttributeMaxDynamicSharedMemorySize, 144480);

    float* p1; cudaGetSymbolAddress((void**)&p1, g_part1);
    float* p2; cudaGetSymbolAddress((void**)&p2, g_part2);
    float* b1; cudaGetSymbolAddress((void**)&b1, g_bn1);
    float* b2; cudaGetSymbolAddress((void**)&b2, g_bn2);

    k_prepw<<<86, 256>>>(conv2_w);
    k_conv1_mmx<<<NB, 224>>>(x, conv1_w, conv1_b);
    k_bnfinal<<<32, 256>>>(bn1_g, bn1_b, p1, b1, 32, 1.f / (float)(NB * 784));
    k_conv2_mma<<<NB, 256, C2M_SMEM>>>(conv2_b);
    k_bnfinal<<<64, 256>>>(bn2_g, bn2_b, p2, b2, 64, 1.f / (float)(NB * 196));
    k_fc1<<<dim3(64, 8), 256>>>(fc1_w);
    k_fc1combine<<<(NB * 128) / 256, 256>>>(fc1_b);
    k_syrk<<<dim3(5, 5, 64), 256>>>();
    k_reduceA<<<66, 256>>>();
    k_phity<<<64, 256>>>(y);
    k_Bfinal<<<6, 256>>>(W_rls);
    k_chol<<<1, 256, 144480>>>(W_rls, sep);
    k_head<<<(NB * 10 + 255) / 256, 256>>>(out);
}

// round 17
// speedup vs baseline: 1.1598x; 1.0251x over previous
#include <cuda_runtime.h>
#include <cuda_bf16.h>
#include <math.h>
#include <cstdint>

#define NB 4096

// ----- scratch (device globals; no allocations) -----
__device__ float  g_h1max[NB * 32 * 196];
__device__ float  g_h1min[NB * 32 * 196];
__device__ float  g_o2max[NB * 64 * 49];
__device__ float  g_o2min[NB * 64 * 49];
__device__ float  g_feat[NB * 128];
__device__ float  g_part1[NB * 64];
__device__ float  g_part2[NB * 128];
__device__ float  g_bn1[64];
__device__ float  g_bn2[128];
__device__ float  g_fcpart[8 * NB * 128];
__device__ float  g_partA[64 * 129 * 129];
__device__ float  g_partB[64 * 1290];
__device__ double g_A[129 * 129];
__device__ double g_Bm[1290];
__device__ float  g_W[1290];
__device__ uint32_t g_Wfh[21888];      // conv2: 72 krows x 76 x uint2
__device__ uint32_t g_Wfl[21888];
__device__ uint32_t g_Wf2h[200704];    // fc1: 784 krows x 128 x uint2
__device__ uint32_t g_Wf2l[200704];

extern __shared__ char dynsmem[];

__device__ __forceinline__ void mma_bf16(float* c, uint32_t a0, uint32_t a1,
                                         uint32_t a2, uint32_t a3,
                                         uint32_t b0, uint32_t b1)
{
    asm volatile(
        "mma.sync.aligned.m16n8k16.row.col.f32.bf16.bf16.f32 "
        "{%0,%1,%2,%3}, {%4,%5,%6,%7}, {%8,%9}, {%0,%1,%2,%3};"
        : "+f"(c[0]), "+f"(c[1]), "+f"(c[2]), "+f"(c[3])
        : "r"(a0), "r"(a1), "r"(a2), "r"(a3), "r"(b0), "r"(b1));
}

__device__ __forceinline__ uint32_t packbf(float v0, float v1)
{
    __nv_bfloat162 p = __floats2bfloat162_rn(v0, v1);
    return *(uint32_t*)&p;
}

// ===== conv1 single pass: raw-conv window max/min + BN stats =====
__global__ __launch_bounds__(224) void k_conv1_mmx(
    const float* __restrict__ x, const float* __restrict__ w, const float* __restrict__ bias)
{
    __shared__ float simg[900], sw[288], sb[32], wred[7][64];
    int n = blockIdx.x, tid = threadIdx.x;
    for (int i = tid; i < 900; i += 224) simg[i] = 0.f;
    for (int i = tid; i < 288; i += 224) sw[i] = w[i];
    if (tid < 32) sb[tid] = bias[tid];
    __syncthreads();
    const float* xi = x + n * 784;
    for (int i = tid; i < 784; i += 224)
        simg[(i / 28 + 1) * 30 + (i % 28) + 1] = xi[i];
    __syncthreads();

    float ls[32], lq[32];
#pragma unroll
    for (int c = 0; c < 32; c++) { ls[c] = 0.f; lq[c] = 0.f; }

    if (tid < 196) {
        int py = tid / 14, px = tid % 14;
        float patch[16];
#pragma unroll
        for (int dy = 0; dy < 4; dy++)
#pragma unroll
            for (int dx = 0; dx < 4; dx++)
                patch[dy * 4 + dx] = simg[(2 * py + dy) * 30 + 2 * px + dx];
#pragma unroll
        for (int oc = 0; oc < 32; oc++) {
            float v[4];
#pragma unroll
            for (int dy = 0; dy < 2; dy++)
#pragma unroll
                for (int dx = 0; dx < 2; dx++) {
                    float a = sb[oc];
#pragma unroll
                    for (int ky = 0; ky < 3; ky++)
#pragma unroll
                        for (int kx = 0; kx < 3; kx++)
                            a = fmaf(sw[oc * 9 + ky * 3 + kx],
                                     patch[(dy + ky) * 4 + dx + kx], a);
                    v[dy * 2 + dx] = a;
                }
            float mx = fmaxf(fmaxf(v[0], v[1]), fmaxf(v[2], v[3]));
            float mn = fminf(fminf(v[0], v[1]), fminf(v[2], v[3]));
            g_h1max[(n * 32 + oc) * 196 + tid] = mx;
            g_h1min[(n * 32 + oc) * 196 + tid] = mn;
            ls[oc] += (v[0] + v[1]) + (v[2] + v[3]);
            lq[oc] = fmaf(v[0], v[0], fmaf(v[1], v[1], fmaf(v[2], v[2], fmaf(v[3], v[3], lq[oc]))));
        }
    }
    int lane = tid & 31, wid = tid >> 5;
#pragma unroll
    for (int oc = 0; oc < 32; oc++) {
        float s = ls[oc], q = lq[oc];
#pragma unroll
        for (int o = 16; o > 0; o >>= 1) {
            s += __shfl_down_sync(0xffffffffu, s, o);
            q += __shfl_down_sync(0xffffffffu, q, o);
        }
        if (lane == 0) { wred[wid][oc] = s; wred[wid][32 + oc] = q; }
    }
    __syncthreads();
    if (tid < 64) {
        float s = 0.f;
#pragma unroll
        for (int w7 = 0; w7 < 7; w7++) s += wred[w7][tid];
        g_part1[n * 64 + tid] = s;
    }
}

// ===== BN finalize =====
__global__ __launch_bounds__(256) void k_bnfinal(
    const float* __restrict__ gamma, const float* __restrict__ beta,
    const float* __restrict__ part, float* __restrict__ bn, int nc, float invN)
{
    int c = blockIdx.x, tid = threadIdx.x;
    float s = 0.f, q = 0.f;
    for (int r = tid; r < NB; r += 256) {
        s += part[r * 2 * nc + c];
        q += part[r * 2 * nc + nc + c];
    }
    __shared__ float ss[256], sq[256];
    ss[tid] = s; sq[tid] = q; __syncthreads();
    for (int o = 128; o > 0; o >>= 1) {
        if (tid < o) { ss[tid] += ss[tid + o]; sq[tid] += sq[tid + o]; }
        __syncthreads();
    }
    if (tid == 0) {
        float mean = ss[0] * invN;
        float var = sq[0] * invN - mean * mean;
        float scale = gamma[c] * rsqrtf(var + 1e-5f);
        bn[c] = scale;
        bn[nc + c] = beta[c] - mean * scale;
    }
}

// ===== conv2 weight fragment prep (once) =====
__global__ __launch_bounds__(256) void k_prepw(const float* __restrict__ cw)
{
    int i = blockIdx.x * 256 + threadIdx.x;
    if (i >= 21888) return;
    int pair = i >> 1, u = i & 1;
    int krow = pair / 76, nb = pair % 76;
    int kt = krow >> 2, t = krow & 3;
    uint32_t hw = 0, lw = 0;
    if (nb < 64) {
        int srow = kt * 8 + t + 4 * u;
        int s9 = srow >> 4, j = srow & 15;
        float w0 = cw[nb * 288 + 2 * j * 9 + s9];
        float w1 = cw[nb * 288 + (2 * j + 1) * 9 + s9];
        __nv_bfloat16 h0 = __float2bfloat16_rn(w0);
        __nv_bfloat16 h1 = __float2bfloat16_rn(w1);
        __nv_bfloat162 hp; hp.x = h0; hp.y = h1;
        hw = *(uint32_t*)&hp;
        lw = packbf(w0 - __bfloat162float(h0), w1 - __bfloat162float(h1));
    }
    g_Wfh[i] = hw;
    g_Wfl[i] = lw;
}

// ===== fc1 weight fragment prep (once): srow pair = (k=2*srow, 2*srow+1) =====
__global__ __launch_bounds__(256) void k_prepfw(const float* __restrict__ fw)
{
    int i = blockIdx.x * 256 + threadIdx.x;
    if (i >= 200704) return;
    int u = i & 1, pe = i >> 1;
    int krow = pe >> 7, nb = pe & 127;
    int kt = krow >> 2, t = krow & 3;
    int srow = kt * 8 + t + 4 * u;
    int k = 2 * srow;
    float w0 = fw[nb * 3136 + k];
    float w1 = fw[nb * 3136 + k + 1];
    __nv_bfloat16 h0 = __float2bfloat16_rn(w0);
    __nv_bfloat16 h1 = __float2bfloat16_rn(w1);
    __nv_bfloat162 hp; hp.x = h0; hp.y = h1;
    g_Wf2h[i] = *(uint32_t*)&hp;
    g_Wf2l[i] = packbf(w0 - __bfloat162float(h0), w1 - __bfloat162float(h1));
}

// ===================== conv2 via mma.sync bf16 split (HMMA), v7 =====================
#define C2M_SMEM 103680

__global__ __launch_bounds__(256, 2) void k_conv2_mma(const float* __restrict__ cb)
{
    uint2* Tah  = (uint2*)dynsmem;
    uint2* Tal  = (uint2*)(dynsmem + 29952);
    uint2* Wbuf = (uint2*)(dynsmem + 59904);
    float* sD   = (float*)dynsmem;
    __shared__ float ssc1[32], ssh1[32], sbias[64];

    int n = blockIdx.x, tid = threadIdx.x;
    int lane = tid & 31, w = tid >> 5;
    int g = lane >> 2, t = lane & 3;

    if (tid < 32) { ssc1[tid] = g_bn1[tid]; ssh1[tid] = g_bn1[32 + tid]; }
    if (tid < 64) sbias[tid] = cb[tid];

    {
        const uint2* gh = (const uint2*)g_Wfh;
        for (int i = tid; i < 5472; i += 256) Wbuf[i] = gh[i];
    }
    for (int i = tid; i < 3744; i += 256) {
        Tah[i] = make_uint2(0u, 0u);
        Tal[i] = make_uint2(0u, 0u);
    }
    __syncthreads();

    const float* mxp = g_h1max + n * 6272;
    const float* mnp = g_h1min + n * 6272;
    __nv_bfloat16* Th16 = (__nv_bfloat16*)Tah;
    __nv_bfloat16* Tl16 = (__nv_bfloat16*)Tal;
    for (int i = tid; i < 6272; i += 256) {
        int ci = i / 196, p = i % 196;
        float sc = ssc1[ci], sh = ssh1[ci];
        float base = (sc >= 0.f) ? mxp[i] : mnp[i];
        float v = fmaxf(fmaf(sc, base, sh), 0.f);
        __nv_bfloat16 hbf = __float2bfloat16_rn(v);
        float lf = v - __bfloat162float(hbf);
        int j = ci >> 1, hh = j >> 3, r = j & 7;
        int tt = r & 3, u = r >> 2;
        int row = (p / 14 + 1) * 16 + (p % 14 + 1);
        int word = row * 26 + (hh * 4 + tt) * 2 + u;
        Th16[word * 2 + (ci & 1)] = hbf;
        Tl16[word * 2 + (ci & 1)] = __float2bfloat16_rn(lf);
    }
    __syncthreads();

    int mg = w & 3, nh = w >> 2;
    int pixa[4], pixb[4], mas[4];
#pragma unroll
    for (int mi = 0; mi < 4; mi++) {
        int mt = mg + 4 * mi;
        bool real = mt < 13;
        int mt2 = real ? mt : mg;
        int ma = mt2 * 16 + g;
        int mb = ma + 8;
        mas[mi] = real ? ma : -1;
        pixa[mi] = ((ma / 14) * 16 + (ma % 14)) * 13;
        pixb[mi] = ((mb / 14) * 16 + (mb % 14)) * 13;
    }
    float acc[4][4][4];
#pragma unroll
    for (int mi = 0; mi < 4; mi++)
#pragma unroll
        for (int nt = 0; nt < 4; nt++)
#pragma unroll
            for (int c = 0; c < 4; c++) acc[mi][nt][c] = 0.f;

    int nb0 = nh * 32 + g;

#pragma unroll 6
    for (int kt = 0; kt < 18; kt++) {
        int s = kt >> 1, hh = kt & 1;
        int off13 = ((s / 3) * 16 + (s % 3)) * 13;
        int wbase = (kt * 4 + t) * 76 + nb0;
        uint2 bh[4];
#pragma unroll
        for (int nt = 0; nt < 4; nt++) bh[nt] = Wbuf[wbase + nt * 8];
        int abase = off13 + hh * 4 + t;
#pragma unroll
        for (int mi = 0; mi < 4; mi++) {
            uint2 uah = Tah[pixa[mi] + abase];
            uint2 ubh = Tah[pixb[mi] + abase];
            uint2 ual = Tal[pixa[mi] + abase];
            uint2 ubl = Tal[pixb[mi] + abase];
#pragma unroll
            for (int nt = 0; nt < 4; nt++) {
                mma_bf16(acc[mi][nt], uah.x, ubh.x, uah.y, ubh.y, bh[nt].x, bh[nt].y);
                mma_bf16(acc[mi][nt], ual.x, ubl.x, ual.y, ubl.y, bh[nt].x, bh[nt].y);
            }
        }
    }
    __syncthreads();
    {
        const uint2* gl = (const uint2*)g_Wfl;
        for (int i = tid; i < 5472; i += 256) Wbuf[i] = gl[i];
    }
    __syncthreads();

#pragma unroll 6
    for (int kt = 0; kt < 18; kt++) {
        int s = kt >> 1, hh = kt & 1;
        int off13 = ((s / 3) * 16 + (s % 3)) * 13;
        int wbase = (kt * 4 + t) * 76 + nb0;
        uint2 bl[4];
#pragma unroll
        for (int nt = 0; nt < 4; nt++) bl[nt] = Wbuf[wbase + nt * 8];
        int abase = off13 + hh * 4 + t;
#pragma unroll
        for (int mi = 0; mi < 4; mi++) {
            uint2 uah = Tah[pixa[mi] + abase];
            uint2 ubh = Tah[pixb[mi] + abase];
#pragma unroll
            for (int nt = 0; nt < 4; nt++)
                mma_bf16(acc[mi][nt], uah.x, ubh.x, uah.y, ubh.y, bl[nt].x, bl[nt].y);
        }
    }
    __syncthreads();

#pragma unroll
    for (int mi = 0; mi < 4; mi++) {
        if (mas[mi] < 0) continue;
        int ma = mas[mi], mb = ma + 8;
#pragma unroll
        for (int nt = 0; nt < 4; nt++) {
            int oc = (nh * 4 + nt) * 8 + t * 2;
            if (ma < 196) {
                sD[oc * 197 + ma] = acc[mi][nt][0];
                sD[(oc + 1) * 197 + ma] = acc[mi][nt][1];
            }
            if (mb < 196) {
                sD[oc * 197 + mb] = acc[mi][nt][2];
                sD[(oc + 1) * 197 + mb] = acc[mi][nt][3];
            }
        }
    }
    __syncthreads();

    if (tid < 128) {
        int oc = tid >> 1, h = tid & 1;
        float b = sbias[oc];
        const float* row = sD + oc * 197;
        float s = 0.f, q = 0.f;
        for (int p2 = h * 98; p2 < h * 98 + 98; p2++) {
            float v = row[p2] + b;
            s += v; q = fmaf(v, v, q);
        }
        float s2 = s + __shfl_xor_sync(0xffffffffu, s, 1);
        float q2 = q + __shfl_xor_sync(0xffffffffu, q, 1);
        if (h == 0) {
            g_part2[n * 128 + oc] = s2;
            g_part2[n * 128 + 64 + oc] = q2;
        }
        int w0 = h * 25, w1 = (h == 0) ? 25 : 49;
        for (int ww = w0; ww < w1; ww++) {
            int wy = ww / 7, wx = ww - wy * 7;
            int pp = wy * 28 + 2 * wx;
            float u0 = row[pp] + b, u1 = row[pp + 1] + b;
            float u2 = row[pp + 14] + b, u3 = row[pp + 15] + b;
            int ob = (n * 64 + oc) * 49 + ww;
            g_o2max[ob] = fmaxf(fmaxf(u0, u1), fmaxf(u2, u3));
            g_o2min[ob] = fminf(fminf(u0, u1), fminf(u2, u3));
        }
    }
}

// ===== fc1 via HMMA split-bf16: D[4096,128] = Phi[4096,3136] x W^T =====
// grid (32, 8): m-block 128 rows, split-K z. Warp = 1 m-tile x 16 n-tiles.
__global__ __launch_bounds__(256) void k_fc1mma()
{
    __shared__ uint32_t Ah[128 * 12], Al[128 * 12];        // A rows, pad stride 12
    __shared__ uint2 Bh[4 * 132], Bl[4 * 132];             // 4 krows, stride 132
    int m0 = blockIdx.x * 128, z = blockIdx.y;
    int kt0 = (196 * z) / 8, kt1 = (196 * (z + 1)) / 8;
    int tid = threadIdx.x, lane = tid & 31, w = tid >> 5;
    int g = lane >> 2, t = lane & 3;

    float acc[16][4];
#pragma unroll
    for (int nt = 0; nt < 16; nt++)
#pragma unroll
        for (int c = 0; c < 4; c++) acc[nt][c] = 0.f;

    __nv_bfloat16* Ah16 = (__nv_bfloat16*)Ah;
    __nv_bfloat16* Al16 = (__nv_bfloat16*)Al;
    const uint2* gh = (const uint2*)g_Wf2h;
    const uint2* gl = (const uint2*)g_Wf2l;

    for (int kt = kt0; kt < kt1; kt++) {
        // stage A: feat[m0+r][kt*16+kk] hi/lo
        for (int i = tid; i < 2048; i += 256) {
            int r = i >> 4, kk = i & 15;
            int kg = kt * 16 + kk;
            int oc = kg / 49, p = kg - oc * 49;
            float sc = __ldg(&g_bn2[oc]), sh = __ldg(&g_bn2[64 + oc]);
            int off = ((m0 + r) * 64 + oc) * 49 + p;
            float base = (sc >= 0.f) ? g_o2max[off] : g_o2min[off];
            float v = fmaxf(fmaf(sc, base, sh), 0.f);
            __nv_bfloat16 hbf = __float2bfloat16_rn(v);
            float lf = v - __bfloat162float(hbf);
            int idx = (r * 12 + (kk >> 1)) * 2 + (kk & 1);
            Ah16[idx] = hbf;
            Al16[idx] = __float2bfloat16_rn(lf);
        }
        // stage B: 4 krows x 128
        for (int i = tid; i < 512; i += 256) {
            int tt = i >> 7, nb = i & 127;
            int gidx = (kt * 4 + tt) * 128 + nb;
            Bh[tt * 132 + nb] = gh[gidx];
            Bl[tt * 132 + nb] = gl[gidx];
        }
        __syncthreads();

        int ra = (w * 16 + g) * 12, rb = ra + 96;          // row g, g+8
        uint32_t ah0 = Ah[ra + t],     ah1 = Ah[rb + t];
        uint32_t ah2 = Ah[ra + 4 + t], ah3 = Ah[rb + 4 + t];
        uint32_t al0 = Al[ra + t],     al1 = Al[rb + t];
        uint32_t al2 = Al[ra + 4 + t], al3 = Al[rb + 4 + t];
        int bbase = t * 132 + g;
#pragma unroll
        for (int nt = 0; nt < 16; nt++) {
            uint2 bh = Bh[bbase + nt * 8];
            uint2 bl = Bl[bbase + nt * 8];
            mma_bf16(acc[nt], ah0, ah1, ah2, ah3, bh.x, bh.y);
            mma_bf16(acc[nt], ah0, ah1, ah2, ah3, bl.x, bl.y);
            mma_bf16(acc[nt], al0, al1, al2, al3, bh.x, bh.y);
        }
        __syncthreads();
    }

    float* pp = g_fcpart + z * (NB * 128);
    int ma = m0 + w * 16 + g, mb = ma + 8;
#pragma unroll
    for (int nt = 0; nt < 16; nt++) {
        int col = nt * 8 + t * 2;
        pp[ma * 128 + col] = acc[nt][0];
        pp[ma * 128 + col + 1] = acc[nt][1];
        pp[mb * 128 + col] = acc[nt][2];
        pp[mb * 128 + col + 1] = acc[nt][3];
    }
}

__global__ __launch_bounds__(256) void k_fc1combine(const float* __restrict__ fb)
{
    int idx = blockIdx.x * 256 + threadIdx.x;
    if (idx >= NB * 128) return;
    float v = fb[idx & 127];
#pragma unroll
    for (int z = 0; z < 8; z++) v += g_fcpart[z * (NB * 128) + idx];
    g_feat[idx] = fmaxf(v, 0.f);
}

// ===== SYRK chunk partials =====
__global__ __launch_bounds__(256) void k_syrk()
{
    __shared__ float As[64][33], Bs[64][33];
    int ti = blockIdx.x, tj = blockIdx.y, ch = blockIdx.z;
    int tid = threadIdx.x, tx = tid & 15, ty = tid >> 4, n0 = ch * 64;
    for (int i = tid; i < 2048; i += 256) {
        int r = i >> 5, c = i & 31;
        int gi = ti * 32 + c, gj = tj * 32 + c;
        As[r][c] = (gi < 128) ? g_feat[(n0 + r) * 128 + gi] : (gi == 128 ? 1.f : 0.f);
        Bs[r][c] = (gj < 128) ? g_feat[(n0 + r) * 128 + gj] : (gj == 128 ? 1.f : 0.f);
    }
    __syncthreads();
    float a00 = 0.f, a01 = 0.f, a10 = 0.f, a11 = 0.f;
#pragma unroll 8
    for (int k = 0; k < 64; k++) {
        float x0 = As[k][2 * ty], x1 = As[k][2 * ty + 1];
        float y0 = Bs[k][2 * tx], y1 = Bs[k][2 * tx + 1];
        a00 = fmaf(x0, y0, a00); a01 = fmaf(x0, y1, a01);
        a10 = fmaf(x1, y0, a10); a11 = fmaf(x1, y1, a11);
    }
    float* pa = g_partA + ch * 16641;
    int gi0 = ti * 32 + 2 * ty, gj0 = tj * 32 + 2 * tx;
    if (gi0 < 129 && gj0 < 129) pa[gi0 * 129 + gj0] = a00;
    if (gi0 < 129 && gj0 + 1 < 129) pa[gi0 * 129 + gj0 + 1] = a01;
    if (gi0 + 1 < 129 && gj0 < 129) pa[(gi0 + 1) * 129 + gj0] = a10;
    if (gi0 + 1 < 129 && gj0 + 1 < 129) pa[(gi0 + 1) * 129 + gj0 + 1] = a11;
}

__global__ __launch_bounds__(256) void k_reduceA()
{
    int o = blockIdx.x * 256 + threadIdx.x;
    if (o >= 16641) return;
    double s = ((o / 129) == (o % 129)) ? 1.0 : 0.0;
    for (int ch = 0; ch < 64; ch++) s += (double)g_partA[ch * 16641 + o];
    g_A[o] = s;
}

// ===== Phi^T Y chunk partials =====
__global__ __launch_bounds__(256) void k_phity(const float* __restrict__ y)
{
    __shared__ float sf[64 * 129], sy[640];
    int ch = blockIdx.x, n0 = ch * 64, tid = threadIdx.x;
    for (int i = tid; i < 8192; i += 256)
        sf[(i >> 7) * 129 + (i & 127)] = g_feat[(n0 + (i >> 7)) * 128 + (i & 127)];
    for (int i = tid; i < 64; i += 256) sf[i * 129 + 128] = 1.f;
    for (int i = tid; i < 640; i += 256) sy[i] = y[n0 * 10 + i];
    __syncthreads();
    for (int o = tid; o < 1290; o += 256) {
        int i = o / 10, c = o % 10;
        float s = 0.f;
        for (int r = 0; r < 64; r++) s = fmaf(sf[r * 129 + i], sy[r * 10 + c], s);
        g_partB[ch * 1290 + o] = s;
    }
}

__global__ __launch_bounds__(256) void k_Bfinal(const float* __restrict__ Wrls)
{
    int o = blockIdx.x * 256 + threadIdx.x;
    if (o >= 1290) return;
    double s = (double)Wrls[o];
    for (int ch = 0; ch < 64; ch++) s += (double)g_partB[ch * 1290 + o];
    g_Bm[o] = s;
}

// ===== fp64 Cholesky + 10-RHS solve =====
__global__ __launch_bounds__(256) void k_chol(const float* __restrict__ Wrls,
                                              const int* __restrict__ sep)
{
    double* A = (double*)dynsmem;
    double* Bv = A + 129 * 130;
    int tid = threadIdx.x;
    if (sep[0] == 0) {
        for (int i = tid; i < 1290; i += 256) g_W[i] = Wrls[i];
        return;
    }
    for (int i = tid; i < 16641; i += 256) A[(i / 129) * 130 + (i % 129)] = g_A[i];
    for (int i = tid; i < 1290; i += 256) Bv[i] = g_Bm[i];
    __syncthreads();
    __shared__ double sinv;
    for (int k = 0; k < 129; k++) {
        if (tid == 0) {
            double d = sqrt(A[k * 130 + k]);
            A[k * 130 + k] = d;
            sinv = 1.0 / d;
        }
        __syncthreads();
        double iv = sinv;
        for (int i = k + 1 + tid; i < 129; i += 256) A[i * 130 + k] *= iv;
        __syncthreads();
        int m = 128 - k;
        for (int t = tid; t < m * m; t += 256) {
            int i = k + 1 + t / m, j = k + 1 + t % m;
            if (j <= i)
                A[i * 130 + j] -= A[i * 130 + k] * A[j * 130 + k];
        }
        __syncthreads();
    }
    for (int k = 0; k < 129; k++) {
        if (tid < 10) Bv[k * 10 + tid] /= A[k * 130 + k];
        __syncthreads();
        for (int t = tid; t < (128 - k) * 10; t += 256) {
            int i = k + 1 + t / 10, c = t % 10;
            Bv[i * 10 + c] -= A[i * 130 + k] * Bv[k * 10 + c];
        }
        __syncthreads();
    }
    for (int k = 128; k >= 0; k--) {
        if (tid < 10) Bv[k * 10 + tid] /= A[k * 130 + k];
        __syncthreads();
        for (int t = tid; t < k * 10; t += 256) {
            int i = t / 10, c = t % 10;
            Bv[i * 10 + c] -= A[k * 130 + i] * Bv[k * 10 + c];
        }
        __syncthreads();
    }
    for (int i = tid; i < 1290; i += 256) g_W[i] = (float)Bv[i];
}

// ===== head =====
__global__ __launch_bounds__(256) void k_head(float* __restrict__ out)
{
    __shared__ float sW[1290];
    int tid = threadIdx.x;
    for (int i = tid; i < 1290; i += 256) sW[i] = g_W[i];
    __syncthreads();
    int idx = blockIdx.x * 256 + tid;
    if (idx >= NB * 10) return;
    int n = idx / 10, c = idx % 10;
    float acc = sW[1280 + c];
    const float* f = g_feat + n * 128;
#pragma unroll 8
    for (int i = 0; i < 128; i++) acc = fmaf(f[i], sW[i * 10 + c], acc);
    out[idx] = acc;
}

extern "C" void kernel_launch(void* const* d_in, const int* in_sizes, int n_in,
                              void* d_out, int out_size)
{
    const float* x       = (const float*)d_in[0];
    const float* y       = (const float*)d_in[1];
    const float* conv1_w = (const float*)d_in[2];
    const float* conv1_b = (const float*)d_in[3];
    const float* bn1_g   = (const float*)d_in[4];
    const float* bn1_b   = (const float*)d_in[5];
    const float* conv2_w = (const float*)d_in[6];
    const float* conv2_b = (const float*)d_in[7];
    const float* bn2_g   = (const float*)d_in[8];
    const float* bn2_b   = (const float*)d_in[9];
    const float* fc1_w   = (const float*)d_in[10];
    const float* fc1_b   = (const float*)d_in[11];
    const float* W_rls   = (const float*)d_in[12];
    const int*   sep     = (const int*)d_in[14];
    float* out = (float*)d_out;

    cudaFuncSetAttribute(k_conv2_mma, cudaFuncAttributeMaxDynamicSharedMemorySize, C2M_SMEM);
    cudaFuncSetAttribute(k_chol, cudaFuncAttributeMaxDynamicSharedMemorySize, 144480);

    float* p1; cudaGetSymbolAddress((void**)&p1, g_part1);
    float* p2; cudaGetSymbolAddress((void**)&p2, g_part2);
    float* b1; cudaGetSymbolAddress((void**)&b1, g_bn1);
    float* b2; cudaGetSymbolAddress((void**)&b2, g_bn2);

    k_prepw<<<86, 256>>>(conv2_w);
    k_prepfw<<<784, 256>>>(fc1_w);
    k_conv1_mmx<<<NB, 224>>>(x, conv1_w, conv1_b);
    k_bnfinal<<<32, 256>>>(bn1_g, bn1_b, p1, b1, 32, 1.f / (float)(NB * 784));
    k_conv2_mma<<<NB, 256, C2M_SMEM>>>(conv2_b);
    k_bnfinal<<<64, 256>>>(bn2_g, bn2_b, p2, b2, 64, 1.f / (float)(NB * 196));
    k_fc1mma<<<dim3(32, 8), 256>>>();
    k_fc1combine<<<(NB * 128) / 256, 256>>>(fc1_b);
    k_syrk<<<dim3(5, 5, 64), 256>>>();
    k_reduceA<<<66, 256>>>();
    k_phity<<<64, 256>>>(y);
    k_Bfinal<<<6, 256>>>(W_rls);
    k_chol<<<1, 256, 144480>>>(W_rls, sep);
    k_head<<<(NB * 10 + 255) / 256, 256>>>(out);
}